// round 2
// baseline (speedup 1.0000x reference)
#include <cuda_runtime.h>
#include <math.h>

// Problem constants
#define NTOK 8192
#define DIM  1024
#define NE   16
#define TOPK 2
#define CAPE 1024          // capacity per expert
#define NS   (NTOK*TOPK)   // 16384 slots

// ---------------- scratch (static device globals; no allocations) ------------
__device__ float              g_gate[NS];        // per-slot gate weight
__device__ unsigned long long g_key[NS];         // packed (score_bits<<14)|(NS-1-slot)
__device__ int                g_eid[NS];         // expert per slot
__device__ int                g_cnt[NE];         // slots per expert
__device__ int                g_list[NE*NS];     // slot ids per expert (unordered)
__device__ unsigned long long g_lkey[NE*NS];     // keys, same order as g_list
__device__ int                g_keptcnt[NE];     // kept per expert (<= CAPE)
__device__ int                g_kept[NE*CAPE];   // kept slot ids per expert
__device__ unsigned char      g_keep[NS];        // keep flag per slot
__device__ float              g_Y[(size_t)NS*DIM]; // expert outputs per slot (64MB)

// ---------------- kernel 0: reset counters ----------------------------------
__global__ void init_kernel() {
    int t = threadIdx.x;
    if (t < NE) { g_cnt[t] = 0; g_keptcnt[t] = 0; }
}

// ---------------- kernel 1: gating (one warp per token) ----------------------
__global__ void gate_kernel(const float* __restrict__ x,
                            const float* __restrict__ gw,
                            const float* __restrict__ gb) {
    int warp = (blockIdx.x * blockDim.x + threadIdx.x) >> 5;
    int lane = threadIdx.x & 31;
    if (warp >= NTOK) return;
    const float* xr = x + (size_t)warp * DIM;

    float acc[NE];
#pragma unroll
    for (int e = 0; e < NE; e++) acc[e] = 0.f;

    for (int i = 0; i < DIM / 32; i++) {
        int d = lane + 32 * i;
        float xv = xr[d];
        const float4* g4 = (const float4*)(gw + d * NE);
#pragma unroll
        for (int q = 0; q < 4; q++) {
            float4 w = g4[q];
            acc[4*q+0] += xv * w.x;
            acc[4*q+1] += xv * w.y;
            acc[4*q+2] += xv * w.z;
            acc[4*q+3] += xv * w.w;
        }
    }
#pragma unroll
    for (int e = 0; e < NE; e++) {
        float v = acc[e];
#pragma unroll
        for (int o = 16; o > 0; o >>= 1) v += __shfl_xor_sync(0xffffffffu, v, o);
        acc[e] = v;
    }

    if (lane == 0) {
        // top-2 with jax.lax.top_k tie semantics (strict >, lower index wins ties)
        float v0 = -1e30f, v1 = -1e30f;
        int   i0 = 0, i1 = 0;
#pragma unroll
        for (int e = 0; e < NE; e++) {
            float v = acc[e] + gb[e];
            if (v > v0)      { v1 = v0; i1 = i0; v0 = v; i0 = e; }
            else if (v > v1) { v1 = v;  i1 = e; }
        }
        // softmax over [v0, v1]
        float t  = expf(v1 - v0);
        float s  = 1.f / (1.f + t);
        float g0 = s, g1 = t * s;        // g0 >= g1 (token score = g0)

        int s0 = 2 * warp, s1 = s0 + 1;
        g_gate[s0] = g0;  g_gate[s1] = g1;
        g_eid[s0]  = i0;  g_eid[s1]  = i1;
        // ordering key: higher score first, then lower slot index first.
        // score in (0,1] positive -> float bits monotone.
        unsigned long long sb = (unsigned long long)__float_as_uint(g0);
        g_key[s0] = (sb << 14) | (unsigned long long)(NS - 1 - s0);
        g_key[s1] = (sb << 14) | (unsigned long long)(NS - 1 - s1);
    }
}

// ---------------- kernel 2: per-expert slot lists -----------------------------
__global__ void build_kernel() {
    int s = blockIdx.x * blockDim.x + threadIdx.x;
    if (s >= NS) return;
    int e = g_eid[s];
    int pos = atomicAdd(&g_cnt[e], 1);
    g_list[e * NS + pos] = s;
    g_lkey[e * NS + pos] = g_key[s];
}

// ---------------- kernel 3: per-expert capacity ranking ----------------------
// Block e: load that expert's keys into smem, each owned item counts how many
// keys are strictly greater. keep iff rank < CAPE. Keys are unique, so this
// exactly reproduces lexsort((-score, expert)) + pos_in_expert < capacity.
__global__ void rank_kernel() {
    extern __shared__ unsigned long long skey[];
    int e = blockIdx.x;
    int c = g_cnt[e];
    for (int i = threadIdx.x; i < c; i += blockDim.x)
        skey[i] = g_lkey[e * NS + i];
    __syncthreads();

    for (int i0 = threadIdx.x; i0 < c; i0 += blockDim.x * 4) {
        unsigned long long mk[4]; int cnt[4]; int idx[4];
#pragma unroll
        for (int b = 0; b < 4; b++) {
            idx[b] = i0 + b * blockDim.x;
            mk[b]  = (idx[b] < c) ? skey[idx[b]] : 0xFFFFFFFFFFFFFFFFULL;
            cnt[b] = 0;
        }
        for (int j = 0; j < c; j++) {
            unsigned long long kj = skey[j];
#pragma unroll
            for (int b = 0; b < 4; b++) cnt[b] += (kj > mk[b]) ? 1 : 0;
        }
#pragma unroll
        for (int b = 0; b < 4; b++) {
            if (idx[b] < c) {
                int slot = g_list[e * NS + idx[b]];
                bool kp = cnt[b] < CAPE;
                g_keep[slot] = kp ? 1 : 0;
                if (kp) {
                    int p = atomicAdd(&g_keptcnt[e], 1);
                    g_kept[e * CAPE + p] = slot;
                }
            }
        }
    }
}

// ---------------- kernel 4: expert GEMM (gathered rows) ----------------------
// Y[slot, f] = sum_d x[token, d] * W[e, f, d] + b[e, f]   for kept slots.
// 128x128 block tile, BK=16, 256 threads, 8x8 per thread, fma.rn.f32x2 inner.
#define BM 128
#define BN 128
#define BK 16

__global__ __launch_bounds__(256, 2)
void expert_gemm(const float* __restrict__ x,
                 const float* __restrict__ ew,
                 const float* __restrict__ eb) {
    int e    = blockIdx.z;
    int mcnt = g_keptcnt[e];
    int m0   = blockIdx.y * BM;
    if (m0 >= mcnt) return;
    int n0   = blockIdx.x * BN;

    __shared__ float As[BK][BM];
    __shared__ float Bs[BK][BN];
    __shared__ int   stok[BM];
    __shared__ int   sslot[BM];

    int t = threadIdx.x;
    if (t < BM) {
        int mi   = m0 + t;
        int slot = (mi < mcnt) ? g_kept[e * CAPE + mi] : -1;
        sslot[t] = slot;
        stok[t]  = (slot >= 0) ? (slot >> 1) : 0;   // token = slot / K
    }
    __syncthreads();

    int tx = t & 15;        // n-group (8 cols)
    int ty = t >> 4;        // m-group (8 rows)

    unsigned long long acc[8][4];   // 8 rows x 4 f32x2 (8 cols)
#pragma unroll
    for (int i = 0; i < 8; i++)
#pragma unroll
        for (int j = 0; j < 4; j++) acc[i][j] = 0ull;

    int lrow = t & 127;
    int lq   = t >> 7;      // 0..1
    const float* wbase = ew + (size_t)e * DIM * DIM;
    const float* arow  = x + (size_t)stok[lrow] * DIM;
    const float* brow  = wbase + (size_t)(n0 + lrow) * DIM;

    for (int k0 = 0; k0 < DIM; k0 += BK) {
#pragma unroll
        for (int h = 0; h < 2; h++) {
            int kq = lq + 2 * h;     // 0..3
            float4 v = *(const float4*)(arow + k0 + 4 * kq);
            As[4*kq+0][lrow] = v.x; As[4*kq+1][lrow] = v.y;
            As[4*kq+2][lrow] = v.z; As[4*kq+3][lrow] = v.w;
            float4 w = *(const float4*)(brow + k0 + 4 * kq);
            Bs[4*kq+0][lrow] = w.x; Bs[4*kq+1][lrow] = w.y;
            Bs[4*kq+2][lrow] = w.z; Bs[4*kq+3][lrow] = w.w;
        }
        __syncthreads();

#pragma unroll
        for (int k = 0; k < BK; k++) {
            float4 a0 = *(const float4*)&As[k][ty * 8];
            float4 a1 = *(const float4*)&As[k][ty * 8 + 4];
            union { float4 f; unsigned long long u[2]; } b0, b1;
            b0.f = *(const float4*)&Bs[k][tx * 8];
            b1.f = *(const float4*)&Bs[k][tx * 8 + 4];
            unsigned long long bb[4] = { b0.u[0], b0.u[1], b1.u[0], b1.u[1] };
            float av[8] = { a0.x, a0.y, a0.z, a0.w, a1.x, a1.y, a1.z, a1.w };
#pragma unroll
            for (int i = 0; i < 8; i++) {
                unsigned long long ap;
                unsigned int ai = __float_as_uint(av[i]);
                asm("mov.b64 %0, {%1, %1};" : "=l"(ap) : "r"(ai));
#pragma unroll
                for (int j = 0; j < 4; j++)
                    asm("fma.rn.f32x2 %0, %1, %2, %0;"
                        : "+l"(acc[i][j]) : "l"(ap), "l"(bb[j]));
            }
        }
        __syncthreads();
    }

    // epilogue: add bias, scatter rows to per-slot output buffer
#pragma unroll
    for (int i = 0; i < 8; i++) {
        int slot = sslot[ty * 8 + i];
        if (slot < 0) continue;
        float* yr = g_Y + (size_t)slot * DIM + n0 + tx * 8;
        const float* br = eb + (size_t)e * DIM + n0 + tx * 8;
#pragma unroll
        for (int j = 0; j < 4; j++) {
            union { unsigned long long u; float2 f; } v; v.u = acc[i][j];
            float2 bias = *(const float2*)(br + 2 * j);
            float2 o; o.x = v.f.x + bias.x; o.y = v.f.y + bias.y;
            *(float2*)(yr + 2 * j) = o;
        }
    }
}

// ---------------- kernel 5: combine ------------------------------------------
__global__ void combine_kernel(const float* __restrict__ x, float* __restrict__ out) {
    int idx = blockIdx.x * blockDim.x + threadIdx.x;   // over N*D/4
    if (idx >= NTOK * DIM / 4) return;
    int n  = idx >> 8;            // D/4 = 256 float4 per row
    int dq = idx & 255;

    float g0 = g_gate[2 * n], g1 = g_gate[2 * n + 1];
    bool  k0 = g_keep[2 * n] != 0, k1 = g_keep[2 * n + 1] != 0;

    float4 xv = ((const float4*)x)[(size_t)n * 256 + dq];
    float4 y0 = k0 ? ((const float4*)g_Y)[(size_t)(2 * n) * 256 + dq]     : xv;
    float4 y1 = k1 ? ((const float4*)g_Y)[(size_t)(2 * n + 1) * 256 + dq] : xv;

    float4 o;
    o.x = g0 * y0.x + g1 * y1.x;
    o.y = g0 * y0.y + g1 * y1.y;
    o.z = g0 * y0.z + g1 * y1.z;
    o.w = g0 * y0.w + g1 * y1.w;
    ((float4*)out)[idx] = o;
}

// ---------------- launch ------------------------------------------------------
extern "C" void kernel_launch(void* const* d_in, const int* in_sizes, int n_in,
                              void* d_out, int out_size) {
    const float* moe_inp  = (const float*)d_in[0];
    const float* gate_w   = (const float*)d_in[1];
    const float* gate_b   = (const float*)d_in[2];
    const float* expert_w = (const float*)d_in[3];
    const float* expert_b = (const float*)d_in[4];
    float* out = (float*)d_out;

    (void)in_sizes; (void)n_in; (void)out_size;

    // rank kernel needs 128KB dynamic smem (worst case: all slots one expert)
    cudaFuncSetAttribute(rank_kernel, cudaFuncAttributeMaxDynamicSharedMemorySize,
                         NS * (int)sizeof(unsigned long long));

    init_kernel<<<1, 32>>>();
    gate_kernel<<<NTOK / 8, 256>>>(moe_inp, gate_w, gate_b);
    build_kernel<<<NS / 256, 256>>>();
    rank_kernel<<<NE, 256, NS * sizeof(unsigned long long)>>>();
    expert_gemm<<<dim3(DIM / BN, (CAPE + BM - 1) / BM, NE), 256>>>(moe_inp, expert_w, expert_b);
    combine_kernel<<<(NTOK * DIM / 4 + 255) / 256, 256>>>(moe_inp, out);
}

// round 5
// speedup vs baseline: 2.5095x; 2.5095x over previous
#include <cuda_runtime.h>
#include <cuda_bf16.h>
#include <math.h>
#include <stdint.h>

// Problem constants
#define NTOK 8192
#define DIM  1024
#define NE   16
#define CAPE 1024
#define NS   (NTOK*2)

// ---------------- scratch (static device globals) ----------------------------
__device__ float              g_gate[NS];
__device__ unsigned long long g_key[NS];
__device__ int                g_eid[NS];
__device__ int                g_cnt[NE];
__device__ int                g_list[NE*NS];
__device__ unsigned long long g_lkey[NE*NS];
__device__ int                g_keptcnt[NE];
__device__ int                g_kept[NE*CAPE];
__device__ unsigned char      g_keep[NS];
__device__ float              g_Y[(size_t)NS*DIM];                 // 64MB
__device__ __nv_bfloat16      g_Ag[(size_t)NE*CAPE*2048];          // 64MB: [e][row][hi(1024)|lo(1024)]
__device__ __nv_bfloat16      g_Bw[(size_t)NE*DIM*2048];           // 64MB: [e][f][hi|lo]

// ---------------- helpers (baseline PTX only: sm_80-level features) ----------
__device__ __forceinline__ uint32_t smem_u32(const void* p) {
    uint32_t a;
    asm("{ .reg .u64 t; cvta.to.shared.u64 t, %1; cvt.u32.u64 %0, t; }" : "=r"(a) : "l"(p));
    return a;
}
__device__ __forceinline__ void cp16(uint32_t d, const void* s) {
    asm volatile("cp.async.cg.shared.global [%0], [%1], 16;" :: "r"(d), "l"(s));
}
__device__ __forceinline__ void cp_commit() {
    asm volatile("cp.async.commit_group;" ::: "memory");
}
__device__ __forceinline__ void ldmx4(uint32_t* r, uint32_t addr) {
    asm volatile("ldmatrix.sync.aligned.m8n8.x4.shared.b16 {%0,%1,%2,%3}, [%4];"
                 : "=r"(r[0]), "=r"(r[1]), "=r"(r[2]), "=r"(r[3]) : "r"(addr));
}
__device__ __forceinline__ void mma_bf16(float* c, const uint32_t* a, uint32_t b0, uint32_t b1) {
    asm volatile("mma.sync.aligned.m16n8k16.row.col.f32.bf16.bf16.f32 "
                 "{%0,%1,%2,%3}, {%4,%5,%6,%7}, {%8,%9}, {%0,%1,%2,%3};"
                 : "+f"(c[0]), "+f"(c[1]), "+f"(c[2]), "+f"(c[3])
                 : "r"(a[0]), "r"(a[1]), "r"(a[2]), "r"(a[3]), "r"(b0), "r"(b1));
}
__device__ __forceinline__ unsigned short f2bf_bits(float f) {
    __nv_bfloat16 h = __float2bfloat16(f);
    return *reinterpret_cast<unsigned short*>(&h);
}

// ---------------- kernel 0: reset counters -----------------------------------
__global__ void init_kernel() {
    int t = threadIdx.x;
    if (t < NE) { g_cnt[t] = 0; g_keptcnt[t] = 0; }
}

// ---------------- kernel 1: gating (one warp per token) ----------------------
__global__ void gate_kernel(const float* __restrict__ x,
                            const float* __restrict__ gw,
                            const float* __restrict__ gb) {
    int warp = (blockIdx.x * blockDim.x + threadIdx.x) >> 5;
    int lane = threadIdx.x & 31;
    if (warp >= NTOK) return;
    const float* xr = x + (size_t)warp * DIM;

    float acc[NE];
#pragma unroll
    for (int e = 0; e < NE; e++) acc[e] = 0.f;

    for (int i = 0; i < DIM / 32; i++) {
        int d = lane + 32 * i;
        float xv = xr[d];
        const float4* g4 = (const float4*)(gw + d * NE);
#pragma unroll
        for (int q = 0; q < 4; q++) {
            float4 w = g4[q];
            acc[4*q+0] += xv * w.x;
            acc[4*q+1] += xv * w.y;
            acc[4*q+2] += xv * w.z;
            acc[4*q+3] += xv * w.w;
        }
    }
#pragma unroll
    for (int e = 0; e < NE; e++) {
        float v = acc[e];
#pragma unroll
        for (int o = 16; o > 0; o >>= 1) v += __shfl_xor_sync(0xffffffffu, v, o);
        acc[e] = v;
    }

    if (lane == 0) {
        float v0 = -1e30f, v1 = -1e30f;
        int   i0 = 0, i1 = 0;
#pragma unroll
        for (int e = 0; e < NE; e++) {
            float v = acc[e] + gb[e];
            if (v > v0)      { v1 = v0; i1 = i0; v0 = v; i0 = e; }
            else if (v > v1) { v1 = v;  i1 = e; }
        }
        float t  = expf(v1 - v0);
        float s  = 1.f / (1.f + t);
        float g0 = s, g1 = t * s;

        int s0 = 2 * warp, s1 = s0 + 1;
        g_gate[s0] = g0;  g_gate[s1] = g1;
        g_eid[s0]  = i0;  g_eid[s1]  = i1;
        unsigned long long sb = (unsigned long long)__float_as_uint(g0);
        g_key[s0] = (sb << 14) | (unsigned long long)(NS - 1 - s0);
        g_key[s1] = (sb << 14) | (unsigned long long)(NS - 1 - s1);
    }
}

// ---------------- kernel 2: per-expert slot lists -----------------------------
__global__ void build_kernel() {
    int s = blockIdx.x * blockDim.x + threadIdx.x;
    if (s >= NS) return;
    int e = g_eid[s];
    int pos = atomicAdd(&g_cnt[e], 1);
    g_list[e * NS + pos] = s;
    g_lkey[e * NS + pos] = g_key[s];
}

// ---------------- kernel 3: per-expert capacity ranking (4 blocks/expert) ----
__global__ void rank_kernel() {
    extern __shared__ unsigned long long skey[];
    int e = blockIdx.x;
    int q = blockIdx.y;
    int c = g_cnt[e];
    for (int i = threadIdx.x; i < c; i += blockDim.x)
        skey[i] = g_lkey[e * NS + i];
    __syncthreads();

    int chunk = (c + 3) >> 2;
    int lo = q * chunk;
    int hi = min(c, lo + chunk);

    for (int i0 = lo + threadIdx.x; i0 < hi; i0 += blockDim.x * 4) {
        unsigned long long mk[4]; int cnt[4]; int idx[4];
#pragma unroll
        for (int b = 0; b < 4; b++) {
            idx[b] = i0 + b * blockDim.x;
            mk[b]  = (idx[b] < hi) ? skey[idx[b]] : 0xFFFFFFFFFFFFFFFFULL;
            cnt[b] = 0;
        }
        for (int j = 0; j < c; j++) {
            unsigned long long kj = skey[j];
#pragma unroll
            for (int b = 0; b < 4; b++) cnt[b] += (kj > mk[b]) ? 1 : 0;
        }
#pragma unroll
        for (int b = 0; b < 4; b++) {
            if (idx[b] < hi) {
                int slot = g_list[e * NS + idx[b]];
                bool kp = cnt[b] < CAPE;
                g_keep[slot] = kp ? 1 : 0;
                if (kp) {
                    int p = atomicAdd(&g_keptcnt[e], 1);
                    g_kept[e * CAPE + p] = slot;
                }
            }
        }
    }
}

// ---------------- kernel 4a: convert expert weights to bf16 hi/lo ------------
__global__ void convert_w_kernel(const float* __restrict__ ew) {
    size_t i4 = (size_t)blockIdx.x * blockDim.x + threadIdx.x;
    size_t g  = i4 * 4;
    size_t r  = g >> 10;
    int    d  = (int)(g & 1023);
    float4 v  = *(const float4*)(ew + g);

    unsigned short h0 = f2bf_bits(v.x), h1 = f2bf_bits(v.y);
    unsigned short h2 = f2bf_bits(v.z), h3 = f2bf_bits(v.w);
    float r0 = v.x - __bfloat162float(*(__nv_bfloat16*)&h0);
    float r1 = v.y - __bfloat162float(*(__nv_bfloat16*)&h1);
    float r2 = v.z - __bfloat162float(*(__nv_bfloat16*)&h2);
    float r3 = v.w - __bfloat162float(*(__nv_bfloat16*)&h3);
    unsigned short l0 = f2bf_bits(r0), l1 = f2bf_bits(r1);
    unsigned short l2 = f2bf_bits(r2), l3 = f2bf_bits(r3);

    uint2 hv = make_uint2((uint32_t)h0 | ((uint32_t)h1 << 16),
                          (uint32_t)h2 | ((uint32_t)h3 << 16));
    uint2 lv = make_uint2((uint32_t)l0 | ((uint32_t)l1 << 16),
                          (uint32_t)l2 | ((uint32_t)l3 << 16));
    *(uint2*)(g_Bw + r * 2048 + d)        = hv;
    *(uint2*)(g_Bw + r * 2048 + 1024 + d) = lv;
}

// ---------------- kernel 4b: gather kept rows, convert to bf16 hi/lo ---------
__global__ void gather_a_kernel(const float* __restrict__ x) {
    int e = blockIdx.y, i = blockIdx.x;
    if (i >= g_keptcnt[e]) return;
    int slot = g_kept[e * CAPE + i];
    const float* xr = x + (size_t)(slot >> 1) * DIM;
    __nv_bfloat16* oh = g_Ag + (size_t)(e * CAPE + i) * 2048;

    int d = threadIdx.x * 8;
    float4 v0 = *(const float4*)(xr + d);
    float4 v1 = *(const float4*)(xr + d + 4);
    float f[8] = { v0.x, v0.y, v0.z, v0.w, v1.x, v1.y, v1.z, v1.w };
    unsigned short hb[8], lb[8];
#pragma unroll
    for (int j = 0; j < 8; j++) {
        hb[j] = f2bf_bits(f[j]);
        lb[j] = f2bf_bits(f[j] - __bfloat162float(*(__nv_bfloat16*)&hb[j]));
    }
    uint4 hv = make_uint4((uint32_t)hb[0] | ((uint32_t)hb[1] << 16),
                          (uint32_t)hb[2] | ((uint32_t)hb[3] << 16),
                          (uint32_t)hb[4] | ((uint32_t)hb[5] << 16),
                          (uint32_t)hb[6] | ((uint32_t)hb[7] << 16));
    uint4 lv = make_uint4((uint32_t)lb[0] | ((uint32_t)lb[1] << 16),
                          (uint32_t)lb[2] | ((uint32_t)lb[3] << 16),
                          (uint32_t)lb[4] | ((uint32_t)lb[5] << 16),
                          (uint32_t)lb[6] | ((uint32_t)lb[7] << 16));
    *(uint4*)(oh + d)        = hv;
    *(uint4*)(oh + 1024 + d) = lv;
}

// ---------------- kernel 5: warp-MMA (HMMA) expert GEMM ----------------------
// Y[slot, n] = sum over fused K=3072 (hi*hi + hi*lo + lo*hi) + bias.
// BM=128, BN=128, BK=32, 3-stage cp.async, 8 warps (4m x 2n), warp tile 32x64.
#define GBM 128
#define GBN 128
#define NKC 96
#define STAGE_BYTES 16384                       // A 8KB + B 8KB
#define GEMM_SMEM (3*STAGE_BYTES + GBM*4)

struct GCtx {
    const __nv_bfloat16* Ab;
    const __nv_bfloat16* Bb;
    uint32_t sb;
    int t;
};

__device__ __forceinline__ void g_load(const GCtx& c, int kc) {
    int seg    = kc >> 5;
    int within = (kc & 31) * 32;
    int a_k = (seg == 2) ? (1024 + within) : within;
    int b_k = (seg == 1) ? (1024 + within) : within;
    uint32_t st = c.sb + (kc % 3) * STAGE_BYTES;
#pragma unroll
    for (int j = 0; j < 2; j++) {               // A: 128 rows x 4 chunks(16B)
        int s = c.t + 256 * j;
        int row = s >> 2, ch = s & 3;
        uint32_t dst = st + row * 64 + ((ch ^ ((row >> 1) & 3)) << 4);
        cp16(dst, c.Ab + (size_t)row * 2048 + a_k + ch * 8);
    }
#pragma unroll
    for (int j = 0; j < 2; j++) {               // B: 128 rows x 4 chunks(16B)
        int s = c.t + 256 * j;
        int row = s >> 2, ch = s & 3;
        uint32_t dst = st + 8192 + row * 64 + ((ch ^ ((row >> 1) & 3)) << 4);
        cp16(dst, c.Bb + (size_t)row * 2048 + b_k + ch * 8);
    }
    cp_commit();
}

__global__ void __launch_bounds__(256, 2)
moe_gemm_mma(const float* __restrict__ eb) {
    extern __shared__ char smem[];
    int e    = blockIdx.z;
    int mcnt = g_keptcnt[e];
    int m0   = blockIdx.y * GBM;
    if (m0 >= mcnt) return;
    int n0   = blockIdx.x * GBN;

    uint32_t sb = smem_u32(smem);
    int t = threadIdx.x;
    int w = t >> 5, l = t & 31;
    int wm = w & 3, wn = w >> 2;

    int* sslot = (int*)(smem + 3 * STAGE_BYTES);
    if (t < GBM) {
        int mi = m0 + t;
        sslot[t] = (mi < mcnt) ? g_kept[e * CAPE + mi] : -1;
    }

    GCtx c;
    c.Ab = g_Ag + (size_t)(e * CAPE + m0) * 2048;
    c.Bb = g_Bw + (size_t)(e * DIM  + n0) * 2048;
    c.sb = sb;
    c.t  = t;

    g_load(c, 0);
    g_load(c, 1);

    float acc[2][8][4];
#pragma unroll
    for (int i = 0; i < 2; i++)
#pragma unroll
        for (int j = 0; j < 8; j++)
#pragma unroll
            for (int q = 0; q < 4; q++) acc[i][j][q] = 0.f;

    int sub = l >> 3, lr = l & 7;
    int a_row = wm * 32 + lr + ((sub & 1) << 3);   // + mt*16
    int a_cs  = sub >> 1;
    int b_row = wn * 64 + lr + ((sub >> 1) << 3);  // + j*16
    int b_cs  = sub & 1;

    for (int kc = 0; kc < NKC; kc++) {
        asm volatile("cp.async.wait_group 1;" ::: "memory");
        __syncthreads();
        uint32_t sA = sb + (kc % 3) * STAGE_BYTES;
        uint32_t sB = sA + 8192;
#pragma unroll
        for (int ks = 0; ks < 2; ks++) {
            uint32_t areg[2][4];
#pragma unroll
            for (int mt = 0; mt < 2; mt++) {
                int row = a_row + mt * 16;
                int kch = ks * 2 + a_cs;
                ldmx4(areg[mt], sA + row * 64 + ((kch ^ ((row >> 1) & 3)) << 4));
            }
#pragma unroll
            for (int j = 0; j < 4; j++) {
                int row = b_row + j * 16;
                int kch = ks * 2 + b_cs;
                uint32_t breg[4];
                ldmx4(breg, sB + row * 64 + ((kch ^ ((row >> 1) & 3)) << 4));
#pragma unroll
                for (int mt = 0; mt < 2; mt++) {
                    mma_bf16(acc[mt][2*j],   areg[mt], breg[0], breg[1]);
                    mma_bf16(acc[mt][2*j+1], areg[mt], breg[2], breg[3]);
                }
            }
        }
        __syncthreads();
        if (kc + 2 < NKC) g_load(c, kc + 2);
        else cp_commit();
    }

    // epilogue: bias + scatter to per-slot Y
    const float* br = eb + (size_t)e * DIM + n0;
#pragma unroll
    for (int mt = 0; mt < 2; mt++) {
        int r0 = wm * 32 + mt * 16 + (l >> 2);
        int s0 = sslot[r0], s1 = sslot[r0 + 8];
#pragma unroll
        for (int nt = 0; nt < 8; nt++) {
            int col = wn * 64 + nt * 8 + (l & 3) * 2;
            float2 bv = *(const float2*)(br + col);
            if (s0 >= 0) {
                float2 o; o.x = acc[mt][nt][0] + bv.x; o.y = acc[mt][nt][1] + bv.y;
                *(float2*)(g_Y + (size_t)s0 * DIM + n0 + col) = o;
            }
            if (s1 >= 0) {
                float2 o; o.x = acc[mt][nt][2] + bv.x; o.y = acc[mt][nt][3] + bv.y;
                *(float2*)(g_Y + (size_t)s1 * DIM + n0 + col) = o;
            }
        }
    }
}

// ---------------- kernel 6: combine ------------------------------------------
__global__ void combine_kernel(const float* __restrict__ x, float* __restrict__ out) {
    int idx = blockIdx.x * blockDim.x + threadIdx.x;
    if (idx >= NTOK * DIM / 4) return;
    int n  = idx >> 8;
    int dq = idx & 255;

    float g0 = g_gate[2 * n], g1 = g_gate[2 * n + 1];
    bool  k0 = g_keep[2 * n] != 0, k1 = g_keep[2 * n + 1] != 0;

    float4 xv = ((const float4*)x)[(size_t)n * 256 + dq];
    float4 y0 = k0 ? ((const float4*)g_Y)[(size_t)(2 * n) * 256 + dq]     : xv;
    float4 y1 = k1 ? ((const float4*)g_Y)[(size_t)(2 * n + 1) * 256 + dq] : xv;

    float4 o;
    o.x = g0 * y0.x + g1 * y1.x;
    o.y = g0 * y0.y + g1 * y1.y;
    o.z = g0 * y0.z + g1 * y1.z;
    o.w = g0 * y0.w + g1 * y1.w;
    ((float4*)out)[idx] = o;
}

// ---------------- launch ------------------------------------------------------
extern "C" void kernel_launch(void* const* d_in, const int* in_sizes, int n_in,
                              void* d_out, int out_size) {
    const float* moe_inp  = (const float*)d_in[0];
    const float* gate_w   = (const float*)d_in[1];
    const float* gate_b   = (const float*)d_in[2];
    const float* expert_w = (const float*)d_in[3];
    const float* expert_b = (const float*)d_in[4];
    float* out = (float*)d_out;

    (void)in_sizes; (void)n_in; (void)out_size;

    cudaFuncSetAttribute(rank_kernel, cudaFuncAttributeMaxDynamicSharedMemorySize,
                         NS * (int)sizeof(unsigned long long));
    cudaFuncSetAttribute(moe_gemm_mma, cudaFuncAttributeMaxDynamicSharedMemorySize,
                         GEMM_SMEM);

    init_kernel<<<1, 32>>>();
    gate_kernel<<<NTOK / 8, 256>>>(moe_inp, gate_w, gate_b);
    build_kernel<<<NS / 256, 256>>>();
    rank_kernel<<<dim3(NE, 4), 256, NS * sizeof(unsigned long long)>>>();
    convert_w_kernel<<<(NE * DIM * DIM / 4) / 256, 256>>>(expert_w);
    gather_a_kernel<<<dim3(CAPE, NE), 128>>>(moe_inp);
    moe_gemm_mma<<<dim3(DIM / GBN, CAPE / GBM, NE), 256, GEMM_SMEM>>>(expert_b);
    combine_kernel<<<(NTOK * DIM / 4 + 255) / 256, 256>>>(moe_inp, out);
}

// round 6
// speedup vs baseline: 3.1470x; 1.2540x over previous
#include <cuda_runtime.h>
#include <cuda_fp16.h>
#include <math.h>
#include <stdint.h>

// Problem constants
#define NTOK 8192
#define DIM  1024
#define NE   16
#define CAPE 1024
#define NS   (NTOK*2)

// ---------------- scratch (static device globals) ----------------------------
__device__ float              g_gate[NS];
__device__ unsigned long long g_key[NS];
__device__ int                g_eid[NS];
__device__ int                g_cnt[NE];
__device__ int                g_list[NE*NS];
__device__ unsigned long long g_lkey[NE*NS];
__device__ int                g_keptcnt[NE];
__device__ int                g_kept[NE*CAPE];
__device__ unsigned char      g_keep[NS];
__device__ float              g_Y[(size_t)NS*DIM];           // 64MB
__device__ __half             g_Ag[(size_t)NE*CAPE*2048];    // 64MB: [e][row][hi | hi/1024]
__device__ __half             g_Bw[(size_t)NE*DIM*2048];     // 64MB: [e][f][hi | lo*1024]

// ---------------- helpers (baseline PTX only: sm_80-level features) ----------
__device__ __forceinline__ uint32_t smem_u32(const void* p) {
    uint32_t a;
    asm("{ .reg .u64 t; cvta.to.shared.u64 t, %1; cvt.u32.u64 %0, t; }" : "=r"(a) : "l"(p));
    return a;
}
__device__ __forceinline__ void cp16(uint32_t d, const void* s) {
    asm volatile("cp.async.cg.shared.global [%0], [%1], 16;" :: "r"(d), "l"(s));
}
__device__ __forceinline__ void cp_commit() {
    asm volatile("cp.async.commit_group;" ::: "memory");
}
__device__ __forceinline__ void ldmx4(uint32_t* r, uint32_t addr) {
    asm volatile("ldmatrix.sync.aligned.m8n8.x4.shared.b16 {%0,%1,%2,%3}, [%4];"
                 : "=r"(r[0]), "=r"(r[1]), "=r"(r[2]), "=r"(r[3]) : "r"(addr));
}
__device__ __forceinline__ void mma_f16(float* c, const uint32_t* a, uint32_t b0, uint32_t b1) {
    asm volatile("mma.sync.aligned.m16n8k16.row.col.f32.f16.f16.f32 "
                 "{%0,%1,%2,%3}, {%4,%5,%6,%7}, {%8,%9}, {%0,%1,%2,%3};"
                 : "+f"(c[0]), "+f"(c[1]), "+f"(c[2]), "+f"(c[3])
                 : "r"(a[0]), "r"(a[1]), "r"(a[2]), "r"(a[3]), "r"(b0), "r"(b1));
}

// ---------------- kernel 0: reset counters -----------------------------------
__global__ void init_kernel() {
    int t = threadIdx.x;
    if (t < NE) { g_cnt[t] = 0; g_keptcnt[t] = 0; }
}

// ---------------- kernel 1: gating (one warp per token) ----------------------
__global__ void gate_kernel(const float* __restrict__ x,
                            const float* __restrict__ gw,
                            const float* __restrict__ gb) {
    int warp = (blockIdx.x * blockDim.x + threadIdx.x) >> 5;
    int lane = threadIdx.x & 31;
    if (warp >= NTOK) return;
    const float* xr = x + (size_t)warp * DIM;

    float acc[NE];
#pragma unroll
    for (int e = 0; e < NE; e++) acc[e] = 0.f;

    for (int i = 0; i < DIM / 32; i++) {
        int d = lane + 32 * i;
        float xv = xr[d];
        const float4* g4 = (const float4*)(gw + d * NE);
#pragma unroll
        for (int q = 0; q < 4; q++) {
            float4 w = g4[q];
            acc[4*q+0] += xv * w.x;
            acc[4*q+1] += xv * w.y;
            acc[4*q+2] += xv * w.z;
            acc[4*q+3] += xv * w.w;
        }
    }
#pragma unroll
    for (int e = 0; e < NE; e++) {
        float v = acc[e];
#pragma unroll
        for (int o = 16; o > 0; o >>= 1) v += __shfl_xor_sync(0xffffffffu, v, o);
        acc[e] = v;
    }

    if (lane == 0) {
        float v0 = -1e30f, v1 = -1e30f;
        int   i0 = 0, i1 = 0;
#pragma unroll
        for (int e = 0; e < NE; e++) {
            float v = acc[e] + gb[e];
            if (v > v0)      { v1 = v0; i1 = i0; v0 = v; i0 = e; }
            else if (v > v1) { v1 = v;  i1 = e; }
        }
        float t  = expf(v1 - v0);
        float s  = 1.f / (1.f + t);
        float g0 = s, g1 = t * s;

        int s0 = 2 * warp, s1 = s0 + 1;
        g_gate[s0] = g0;  g_gate[s1] = g1;
        g_eid[s0]  = i0;  g_eid[s1]  = i1;
        unsigned long long sb = (unsigned long long)__float_as_uint(g0);
        g_key[s0] = (sb << 14) | (unsigned long long)(NS - 1 - s0);
        g_key[s1] = (sb << 14) | (unsigned long long)(NS - 1 - s1);
    }
}

// ---------------- kernel 2: per-expert slot lists -----------------------------
__global__ void build_kernel() {
    int s = blockIdx.x * blockDim.x + threadIdx.x;
    if (s >= NS) return;
    int e = g_eid[s];
    int pos = atomicAdd(&g_cnt[e], 1);
    g_list[e * NS + pos] = s;
    g_lkey[e * NS + pos] = g_key[s];
}

// ---------------- kernel 3: per-expert capacity ranking (16 blocks/expert) ---
__global__ void rank_kernel() {
    extern __shared__ unsigned long long skey[];
    int e = blockIdx.x;
    int q = blockIdx.y;
    int c = g_cnt[e];
    for (int i = threadIdx.x; i < c; i += blockDim.x)
        skey[i] = g_lkey[e * NS + i];
    __syncthreads();

    int chunk = (c + 15) >> 4;
    int lo = q * chunk;
    int hi = min(c, lo + chunk);

    for (int i0 = lo + threadIdx.x; i0 < hi; i0 += blockDim.x * 2) {
        unsigned long long mk[2]; int cnt[2]; int idx[2];
#pragma unroll
        for (int b = 0; b < 2; b++) {
            idx[b] = i0 + b * blockDim.x;
            mk[b]  = (idx[b] < hi) ? skey[idx[b]] : 0xFFFFFFFFFFFFFFFFULL;
            cnt[b] = 0;
        }
        for (int j = 0; j < c; j++) {
            unsigned long long kj = skey[j];
#pragma unroll
            for (int b = 0; b < 2; b++) cnt[b] += (kj > mk[b]) ? 1 : 0;
        }
#pragma unroll
        for (int b = 0; b < 2; b++) {
            if (idx[b] < hi) {
                int slot = g_list[e * NS + idx[b]];
                bool kp = cnt[b] < CAPE;
                g_keep[slot] = kp ? 1 : 0;
                if (kp) {
                    int p = atomicAdd(&g_keptcnt[e], 1);
                    g_kept[e * CAPE + p] = slot;
                }
            }
        }
    }
}

// ---------------- kernel 4a: convert expert weights to fp16 hi / lo*1024 -----
__global__ void convert_w_kernel(const float* __restrict__ ew) {
    size_t i4 = (size_t)blockIdx.x * blockDim.x + threadIdx.x;
    size_t g  = i4 * 4;
    size_t r  = g >> 10;
    int    d  = (int)(g & 1023);
    float4 v  = *(const float4*)(ew + g);

    float f[4] = { v.x, v.y, v.z, v.w };
    __half hi[4], lo[4];
#pragma unroll
    for (int j = 0; j < 4; j++) {
        hi[j] = __float2half_rn(f[j]);
        lo[j] = __float2half_rn((f[j] - __half2float(hi[j])) * 1024.0f);
    }
    *(uint2*)(g_Bw + r * 2048 + d) =
        make_uint2((uint32_t)__half_as_ushort(hi[0]) | ((uint32_t)__half_as_ushort(hi[1]) << 16),
                   (uint32_t)__half_as_ushort(hi[2]) | ((uint32_t)__half_as_ushort(hi[3]) << 16));
    *(uint2*)(g_Bw + r * 2048 + 1024 + d) =
        make_uint2((uint32_t)__half_as_ushort(lo[0]) | ((uint32_t)__half_as_ushort(lo[1]) << 16),
                   (uint32_t)__half_as_ushort(lo[2]) | ((uint32_t)__half_as_ushort(lo[3]) << 16));
}

// ---------------- kernel 4b: gather kept rows -> fp16 hi / hi/1024 -----------
__global__ void gather_a_kernel(const float* __restrict__ x) {
    int e = blockIdx.y, i = blockIdx.x;
    if (i >= g_keptcnt[e]) return;
    int slot = g_kept[e * CAPE + i];
    const float* xr = x + (size_t)(slot >> 1) * DIM;
    __half* oh = g_Ag + (size_t)(e * CAPE + i) * 2048;

    int d = threadIdx.x * 8;
    float4 v0 = *(const float4*)(xr + d);
    float4 v1 = *(const float4*)(xr + d + 4);
    float f[8] = { v0.x, v0.y, v0.z, v0.w, v1.x, v1.y, v1.z, v1.w };
    unsigned short hb[8], sb[8];
#pragma unroll
    for (int j = 0; j < 8; j++) {
        __half h = __float2half_rn(f[j]);
        hb[j] = __half_as_ushort(h);
        sb[j] = __half_as_ushort(__float2half_rn(__half2float(h) * (1.0f / 1024.0f)));
    }
    *(uint4*)(oh + d) =
        make_uint4((uint32_t)hb[0] | ((uint32_t)hb[1] << 16),
                   (uint32_t)hb[2] | ((uint32_t)hb[3] << 16),
                   (uint32_t)hb[4] | ((uint32_t)hb[5] << 16),
                   (uint32_t)hb[6] | ((uint32_t)hb[7] << 16));
    *(uint4*)(oh + 1024 + d) =
        make_uint4((uint32_t)sb[0] | ((uint32_t)sb[1] << 16),
                   (uint32_t)sb[2] | ((uint32_t)sb[3] << 16),
                   (uint32_t)sb[4] | ((uint32_t)sb[5] << 16),
                   (uint32_t)sb[6] | ((uint32_t)sb[7] << 16));
}

// ---------------- kernel 5: warp-MMA (HMMA) expert GEMM, plain K=2048 --------
// Y[slot, n] = sum_{k<2048} A[row,k]*B[n,k] + bias
//   A = [hi(x) | hi(x)/1024], B = [hi(w) | (w-hi(w))*1024]
// BM=128, BN=128, BK=32, 3-stage cp.async, 8 warps (4m x 2n), warp tile 32x64.
#define GBM 128
#define GBN 128
#define NKC 64
#define STAGE_BYTES 16384                       // A 8KB + B 8KB
#define GEMM_SMEM (3*STAGE_BYTES + GBM*4)

struct GCtx {
    const __half* Ab;
    const __half* Bb;
    uint32_t sb;
    int t;
};

__device__ __forceinline__ void g_load(const GCtx& c, int kc) {
    int k0 = kc * 32;
    uint32_t st = c.sb + (kc % 3) * STAGE_BYTES;
#pragma unroll
    for (int j = 0; j < 2; j++) {               // A: 128 rows x 4 chunks(16B)
        int s = c.t + 256 * j;
        int row = s >> 2, ch = s & 3;
        uint32_t dst = st + row * 64 + ((ch ^ ((row >> 1) & 3)) << 4);
        cp16(dst, c.Ab + (size_t)row * 2048 + k0 + ch * 8);
    }
#pragma unroll
    for (int j = 0; j < 2; j++) {               // B: 128 rows x 4 chunks(16B)
        int s = c.t + 256 * j;
        int row = s >> 2, ch = s & 3;
        uint32_t dst = st + 8192 + row * 64 + ((ch ^ ((row >> 1) & 3)) << 4);
        cp16(dst, c.Bb + (size_t)row * 2048 + k0 + ch * 8);
    }
    cp_commit();
}

__global__ void __launch_bounds__(256, 2)
moe_gemm_mma(const float* __restrict__ eb) {
    extern __shared__ char smem[];
    int e    = blockIdx.z;
    int mcnt = g_keptcnt[e];
    int m0   = blockIdx.y * GBM;
    if (m0 >= mcnt) return;
    int n0   = blockIdx.x * GBN;

    uint32_t sb = smem_u32(smem);
    int t = threadIdx.x;
    int w = t >> 5, l = t & 31;
    int wm = w & 3, wn = w >> 2;

    int* sslot = (int*)(smem + 3 * STAGE_BYTES);
    if (t < GBM) {
        int mi = m0 + t;
        sslot[t] = (mi < mcnt) ? g_kept[e * CAPE + mi] : -1;
    }

    GCtx c;
    c.Ab = g_Ag + (size_t)(e * CAPE + m0) * 2048;
    c.Bb = g_Bw + (size_t)(e * DIM  + n0) * 2048;
    c.sb = sb;
    c.t  = t;

    g_load(c, 0);
    g_load(c, 1);

    float acc[2][8][4];
#pragma unroll
    for (int i = 0; i < 2; i++)
#pragma unroll
        for (int j = 0; j < 8; j++)
#pragma unroll
            for (int q = 0; q < 4; q++) acc[i][j][q] = 0.f;

    int sub = l >> 3, lr = l & 7;
    int a_row = wm * 32 + lr + ((sub & 1) << 3);   // + mt*16
    int a_cs  = sub >> 1;
    int b_row = wn * 64 + lr + ((sub >> 1) << 3);  // + j*16
    int b_cs  = sub & 1;

    for (int kc = 0; kc < NKC; kc++) {
        asm volatile("cp.async.wait_group 1;" ::: "memory");
        __syncthreads();
        uint32_t sA = sb + (kc % 3) * STAGE_BYTES;
        uint32_t sB = sA + 8192;
#pragma unroll
        for (int ks = 0; ks < 2; ks++) {
            uint32_t areg[2][4];
#pragma unroll
            for (int mt = 0; mt < 2; mt++) {
                int row = a_row + mt * 16;
                int kch = ks * 2 + a_cs;
                ldmx4(areg[mt], sA + row * 64 + ((kch ^ ((row >> 1) & 3)) << 4));
            }
#pragma unroll
            for (int j = 0; j < 4; j++) {
                int row = b_row + j * 16;
                int kch = ks * 2 + b_cs;
                uint32_t breg[4];
                ldmx4(breg, sB + row * 64 + ((kch ^ ((row >> 1) & 3)) << 4));
#pragma unroll
                for (int mt = 0; mt < 2; mt++) {
                    mma_f16(acc[mt][2*j],   areg[mt], breg[0], breg[1]);
                    mma_f16(acc[mt][2*j+1], areg[mt], breg[2], breg[3]);
                }
            }
        }
        __syncthreads();
        if (kc + 2 < NKC) g_load(c, kc + 2);
        else cp_commit();
    }

    // epilogue: bias + scatter to per-slot Y
    const float* br = eb + (size_t)e * DIM + n0;
#pragma unroll
    for (int mt = 0; mt < 2; mt++) {
        int r0 = wm * 32 + mt * 16 + (l >> 2);
        int s0 = sslot[r0], s1 = sslot[r0 + 8];
#pragma unroll
        for (int nt = 0; nt < 8; nt++) {
            int col = wn * 64 + nt * 8 + (l & 3) * 2;
            float2 bv = *(const float2*)(br + col);
            if (s0 >= 0) {
                float2 o; o.x = acc[mt][nt][0] + bv.x; o.y = acc[mt][nt][1] + bv.y;
                *(float2*)(g_Y + (size_t)s0 * DIM + n0 + col) = o;
            }
            if (s1 >= 0) {
                float2 o; o.x = acc[mt][nt][2] + bv.x; o.y = acc[mt][nt][3] + bv.y;
                *(float2*)(g_Y + (size_t)s1 * DIM + n0 + col) = o;
            }
        }
    }
}

// ---------------- kernel 6: combine ------------------------------------------
__global__ void combine_kernel(const float* __restrict__ x, float* __restrict__ out) {
    int idx = blockIdx.x * blockDim.x + threadIdx.x;
    if (idx >= NTOK * DIM / 4) return;
    int n  = idx >> 8;
    int dq = idx & 255;

    float g0 = g_gate[2 * n], g1 = g_gate[2 * n + 1];
    bool  k0 = g_keep[2 * n] != 0, k1 = g_keep[2 * n + 1] != 0;

    float4 xv = ((const float4*)x)[(size_t)n * 256 + dq];
    float4 y0 = k0 ? ((const float4*)g_Y)[(size_t)(2 * n) * 256 + dq]     : xv;
    float4 y1 = k1 ? ((const float4*)g_Y)[(size_t)(2 * n + 1) * 256 + dq] : xv;

    float4 o;
    o.x = g0 * y0.x + g1 * y1.x;
    o.y = g0 * y0.y + g1 * y1.y;
    o.z = g0 * y0.z + g1 * y1.z;
    o.w = g0 * y0.w + g1 * y1.w;
    ((float4*)out)[idx] = o;
}

// ---------------- launch ------------------------------------------------------
extern "C" void kernel_launch(void* const* d_in, const int* in_sizes, int n_in,
                              void* d_out, int out_size) {
    const float* moe_inp  = (const float*)d_in[0];
    const float* gate_w   = (const float*)d_in[1];
    const float* gate_b   = (const float*)d_in[2];
    const float* expert_w = (const float*)d_in[3];
    const float* expert_b = (const float*)d_in[4];
    float* out = (float*)d_out;

    (void)in_sizes; (void)n_in; (void)out_size;

    cudaFuncSetAttribute(rank_kernel, cudaFuncAttributeMaxDynamicSharedMemorySize,
                         NS * (int)sizeof(unsigned long long));
    cudaFuncSetAttribute(moe_gemm_mma, cudaFuncAttributeMaxDynamicSharedMemorySize,
                         GEMM_SMEM);

    init_kernel<<<1, 32>>>();
    gate_kernel<<<NTOK / 8, 256>>>(moe_inp, gate_w, gate_b);
    build_kernel<<<NS / 256, 256>>>();
    rank_kernel<<<dim3(NE, 16), 256, NS * sizeof(unsigned long long)>>>();
    convert_w_kernel<<<(NE * DIM * DIM / 4) / 256, 256>>>(expert_w);
    gather_a_kernel<<<dim3(CAPE, NE), 128>>>(moe_inp);
    moe_gemm_mma<<<dim3(DIM / GBN, CAPE / GBM, NE), 256, GEMM_SMEM>>>(expert_b);
    combine_kernel<<<(NTOK * DIM / 4 + 255) / 256, 256>>>(moe_inp, out);
}

// round 7
// speedup vs baseline: 3.9607x; 1.2585x over previous
#include <cuda_runtime.h>
#include <cuda_fp16.h>
#include <math.h>
#include <stdint.h>

// Problem constants
#define NTOK 8192
#define DIM  1024
#define NE   16
#define CAPE 1024
#define NS   (NTOK*2)

// ---------------- scratch (static device globals) ----------------------------
__device__ float              g_gate[NS];
__device__ unsigned long long g_key[NS];
__device__ int                g_eid[NS];
__device__ int                g_cnt[NE];
__device__ int                g_list[NE*NS];
__device__ unsigned long long g_lkey[NE*NS];
__device__ int                g_keptcnt[NE];
__device__ int                g_kept[NE*CAPE];
__device__ unsigned char      g_keep[NS];
__device__ float              g_Y[(size_t)NS*DIM];           // 64MB
__device__ __half             g_Ag[(size_t)NE*CAPE*DIM];     // 32MB: [e][row][k] fp16(x)
__device__ __half             g_Bw[(size_t)NE*DIM*DIM];      // 32MB: flat fp16(w)

// ---------------- helpers (baseline PTX only: sm_80-level features) ----------
__device__ __forceinline__ uint32_t smem_u32(const void* p) {
    uint32_t a;
    asm("{ .reg .u64 t; cvta.to.shared.u64 t, %1; cvt.u32.u64 %0, t; }" : "=r"(a) : "l"(p));
    return a;
}
__device__ __forceinline__ void cp16(uint32_t d, const void* s) {
    asm volatile("cp.async.cg.shared.global [%0], [%1], 16;" :: "r"(d), "l"(s));
}
__device__ __forceinline__ void cp_commit() {
    asm volatile("cp.async.commit_group;" ::: "memory");
}
__device__ __forceinline__ void ldmx4(uint32_t* r, uint32_t addr) {
    asm volatile("ldmatrix.sync.aligned.m8n8.x4.shared.b16 {%0,%1,%2,%3}, [%4];"
                 : "=r"(r[0]), "=r"(r[1]), "=r"(r[2]), "=r"(r[3]) : "r"(addr));
}
__device__ __forceinline__ void mma_f16(float* c, const uint32_t* a, uint32_t b0, uint32_t b1) {
    asm volatile("mma.sync.aligned.m16n8k16.row.col.f32.f16.f16.f32 "
                 "{%0,%1,%2,%3}, {%4,%5,%6,%7}, {%8,%9}, {%0,%1,%2,%3};"
                 : "+f"(c[0]), "+f"(c[1]), "+f"(c[2]), "+f"(c[3])
                 : "r"(a[0]), "r"(a[1]), "r"(a[2]), "r"(a[3]), "r"(b0), "r"(b1));
}

// ---------------- kernel 0: reset counters -----------------------------------
__global__ void init_kernel() {
    int t = threadIdx.x;
    if (t < NE) { g_cnt[t] = 0; g_keptcnt[t] = 0; }
}

// ---------------- kernel 1: gating (one warp per token) ----------------------
__global__ void gate_kernel(const float* __restrict__ x,
                            const float* __restrict__ gw,
                            const float* __restrict__ gb) {
    int warp = (blockIdx.x * blockDim.x + threadIdx.x) >> 5;
    int lane = threadIdx.x & 31;
    if (warp >= NTOK) return;
    const float* xr = x + (size_t)warp * DIM;

    float acc[NE];
#pragma unroll
    for (int e = 0; e < NE; e++) acc[e] = 0.f;

    for (int i = 0; i < DIM / 32; i++) {
        int d = lane + 32 * i;
        float xv = xr[d];
        const float4* g4 = (const float4*)(gw + d * NE);
#pragma unroll
        for (int q = 0; q < 4; q++) {
            float4 w = g4[q];
            acc[4*q+0] += xv * w.x;
            acc[4*q+1] += xv * w.y;
            acc[4*q+2] += xv * w.z;
            acc[4*q+3] += xv * w.w;
        }
    }
#pragma unroll
    for (int e = 0; e < NE; e++) {
        float v = acc[e];
#pragma unroll
        for (int o = 16; o > 0; o >>= 1) v += __shfl_xor_sync(0xffffffffu, v, o);
        acc[e] = v;
    }

    if (lane == 0) {
        float v0 = -1e30f, v1 = -1e30f;
        int   i0 = 0, i1 = 0;
#pragma unroll
        for (int e = 0; e < NE; e++) {
            float v = acc[e] + gb[e];
            if (v > v0)      { v1 = v0; i1 = i0; v0 = v; i0 = e; }
            else if (v > v1) { v1 = v;  i1 = e; }
        }
        float t  = expf(v1 - v0);
        float s  = 1.f / (1.f + t);
        float g0 = s, g1 = t * s;

        int s0 = 2 * warp, s1 = s0 + 1;
        g_gate[s0] = g0;  g_gate[s1] = g1;
        g_eid[s0]  = i0;  g_eid[s1]  = i1;
        unsigned long long sb = (unsigned long long)__float_as_uint(g0);
        g_key[s0] = (sb << 14) | (unsigned long long)(NS - 1 - s0);
        g_key[s1] = (sb << 14) | (unsigned long long)(NS - 1 - s1);
    }
}

// ---------------- kernel 2: per-expert slot lists -----------------------------
__global__ void build_kernel() {
    int s = blockIdx.x * blockDim.x + threadIdx.x;
    if (s >= NS) return;
    int e = g_eid[s];
    int pos = atomicAdd(&g_cnt[e], 1);
    g_list[e * NS + pos] = s;
    g_lkey[e * NS + pos] = g_key[s];
}

// ---------------- kernel 3: capacity ranking (16 blocks/expert, tiled smem) --
#define RTILE 2048
__global__ void rank_kernel() {
    __shared__ unsigned long long tile[RTILE];
    int e = blockIdx.x;
    int q = blockIdx.y;
    int c = g_cnt[e];

    int chunk = (c + 15) >> 4;          // <= 1024 even in worst case
    int lo = q * chunk;
    int hi = min(c, lo + chunk);

    // each thread owns up to 4 items of [lo, hi)
    int idx[4]; unsigned long long mk[4]; int cnt[4];
#pragma unroll
    for (int b = 0; b < 4; b++) {
        idx[b] = lo + threadIdx.x + 256 * b;
        mk[b]  = (idx[b] < hi) ? g_lkey[e * NS + idx[b]] : 0xFFFFFFFFFFFFFFFFULL;
        cnt[b] = 0;
    }

    for (int t0 = 0; t0 < c; t0 += RTILE) {
        int tl = min(c - t0, RTILE);
        __syncthreads();
        for (int i = threadIdx.x; i < tl; i += blockDim.x)
            tile[i] = g_lkey[e * NS + t0 + i];
        __syncthreads();
        for (int j = 0; j < tl; j++) {
            unsigned long long kj = tile[j];
#pragma unroll
            for (int b = 0; b < 4; b++) cnt[b] += (kj > mk[b]) ? 1 : 0;
        }
    }

#pragma unroll
    for (int b = 0; b < 4; b++) {
        if (idx[b] < hi) {
            int slot = g_list[e * NS + idx[b]];
            bool kp = cnt[b] < CAPE;
            g_keep[slot] = kp ? 1 : 0;
            if (kp) {
                int p = atomicAdd(&g_keptcnt[e], 1);
                g_kept[e * CAPE + p] = slot;
            }
        }
    }
}

// ---------------- kernel 4a: convert expert weights to fp16 (flat stream) ----
__global__ void convert_w_kernel(const float* __restrict__ ew) {
    size_t i4 = (size_t)blockIdx.x * blockDim.x + threadIdx.x;
    size_t g  = i4 * 4;
    float4 v  = *(const float4*)(ew + g);
    unsigned short h0 = __half_as_ushort(__float2half_rn(v.x));
    unsigned short h1 = __half_as_ushort(__float2half_rn(v.y));
    unsigned short h2 = __half_as_ushort(__float2half_rn(v.z));
    unsigned short h3 = __half_as_ushort(__float2half_rn(v.w));
    *(uint2*)(g_Bw + g) = make_uint2((uint32_t)h0 | ((uint32_t)h1 << 16),
                                     (uint32_t)h2 | ((uint32_t)h3 << 16));
}

// ---------------- kernel 4b: gather kept rows -> fp16 ------------------------
__global__ void gather_a_kernel(const float* __restrict__ x) {
    int e = blockIdx.y, i = blockIdx.x;
    if (i >= g_keptcnt[e]) return;
    int slot = g_kept[e * CAPE + i];
    const float* xr = x + (size_t)(slot >> 1) * DIM;
    __half* oh = g_Ag + (size_t)(e * CAPE + i) * DIM;

    int d = threadIdx.x * 8;
    float4 v0 = *(const float4*)(xr + d);
    float4 v1 = *(const float4*)(xr + d + 4);
    float f[8] = { v0.x, v0.y, v0.z, v0.w, v1.x, v1.y, v1.z, v1.w };
    unsigned short hb[8];
#pragma unroll
    for (int j = 0; j < 8; j++) hb[j] = __half_as_ushort(__float2half_rn(f[j]));
    *(uint4*)(oh + d) =
        make_uint4((uint32_t)hb[0] | ((uint32_t)hb[1] << 16),
                   (uint32_t)hb[2] | ((uint32_t)hb[3] << 16),
                   (uint32_t)hb[4] | ((uint32_t)hb[5] << 16),
                   (uint32_t)hb[6] | ((uint32_t)hb[7] << 16));
}

// ---------------- kernel 5: warp-MMA (HMMA) expert GEMM, K=1024 --------------
// BM=128, BN=128, BK=32, 3-stage cp.async, 8 warps (4m x 2n), warp tile 32x64.
#define GBM 128
#define GBN 128
#define NKC 32
#define STAGE_BYTES 16384                       // A 8KB + B 8KB
#define GEMM_SMEM (3*STAGE_BYTES + GBM*4)

struct GCtx {
    const __half* Ab;
    const __half* Bb;
    uint32_t sb;
    int t;
};

__device__ __forceinline__ void g_load(const GCtx& c, int kc) {
    int k0 = kc * 32;
    uint32_t st = c.sb + (kc % 3) * STAGE_BYTES;
#pragma unroll
    for (int j = 0; j < 2; j++) {               // A: 128 rows x 4 chunks(16B)
        int s = c.t + 256 * j;
        int row = s >> 2, ch = s & 3;
        uint32_t dst = st + row * 64 + ((ch ^ ((row >> 1) & 3)) << 4);
        cp16(dst, c.Ab + (size_t)row * DIM + k0 + ch * 8);
    }
#pragma unroll
    for (int j = 0; j < 2; j++) {               // B: 128 rows x 4 chunks(16B)
        int s = c.t + 256 * j;
        int row = s >> 2, ch = s & 3;
        uint32_t dst = st + 8192 + row * 64 + ((ch ^ ((row >> 1) & 3)) << 4);
        cp16(dst, c.Bb + (size_t)row * DIM + k0 + ch * 8);
    }
    cp_commit();
}

__global__ void __launch_bounds__(256, 2)
moe_gemm_mma(const float* __restrict__ eb) {
    extern __shared__ char smem[];
    int e    = blockIdx.z;
    int mcnt = g_keptcnt[e];
    int m0   = blockIdx.y * GBM;
    if (m0 >= mcnt) return;
    int n0   = blockIdx.x * GBN;

    uint32_t sb = smem_u32(smem);
    int t = threadIdx.x;
    int w = t >> 5, l = t & 31;
    int wm = w & 3, wn = w >> 2;

    int* sslot = (int*)(smem + 3 * STAGE_BYTES);
    if (t < GBM) {
        int mi = m0 + t;
        sslot[t] = (mi < mcnt) ? g_kept[e * CAPE + mi] : -1;
    }

    GCtx c;
    c.Ab = g_Ag + (size_t)(e * CAPE + m0) * DIM;
    c.Bb = g_Bw + (size_t)(e * DIM  + n0) * DIM;
    c.sb = sb;
    c.t  = t;

    g_load(c, 0);
    g_load(c, 1);

    float acc[2][8][4];
#pragma unroll
    for (int i = 0; i < 2; i++)
#pragma unroll
        for (int j = 0; j < 8; j++)
#pragma unroll
            for (int q = 0; q < 4; q++) acc[i][j][q] = 0.f;

    int sub = l >> 3, lr = l & 7;
    int a_row = wm * 32 + lr + ((sub & 1) << 3);   // + mt*16
    int a_cs  = sub >> 1;
    int b_row = wn * 64 + lr + ((sub >> 1) << 3);  // + j*16
    int b_cs  = sub & 1;

    for (int kc = 0; kc < NKC; kc++) {
        asm volatile("cp.async.wait_group 1;" ::: "memory");
        __syncthreads();
        uint32_t sA = sb + (kc % 3) * STAGE_BYTES;
        uint32_t sB = sA + 8192;
#pragma unroll
        for (int ks = 0; ks < 2; ks++) {
            uint32_t areg[2][4];
#pragma unroll
            for (int mt = 0; mt < 2; mt++) {
                int row = a_row + mt * 16;
                int kch = ks * 2 + a_cs;
                ldmx4(areg[mt], sA + row * 64 + ((kch ^ ((row >> 1) & 3)) << 4));
            }
#pragma unroll
            for (int j = 0; j < 4; j++) {
                int row = b_row + j * 16;
                int kch = ks * 2 + b_cs;
                uint32_t breg[4];
                ldmx4(breg, sB + row * 64 + ((kch ^ ((row >> 1) & 3)) << 4));
#pragma unroll
                for (int mt = 0; mt < 2; mt++) {
                    mma_f16(acc[mt][2*j],   areg[mt], breg[0], breg[1]);
                    mma_f16(acc[mt][2*j+1], areg[mt], breg[2], breg[3]);
                }
            }
        }
        __syncthreads();
        if (kc + 2 < NKC) g_load(c, kc + 2);
        else cp_commit();
    }

    // epilogue: bias + scatter to per-slot Y
    const float* br = eb + (size_t)e * DIM + n0;
#pragma unroll
    for (int mt = 0; mt < 2; mt++) {
        int r0 = wm * 32 + mt * 16 + (l >> 2);
        int s0 = sslot[r0], s1 = sslot[r0 + 8];
#pragma unroll
        for (int nt = 0; nt < 8; nt++) {
            int col = wn * 64 + nt * 8 + (l & 3) * 2;
            float2 bv = *(const float2*)(br + col);
            if (s0 >= 0) {
                float2 o; o.x = acc[mt][nt][0] + bv.x; o.y = acc[mt][nt][1] + bv.y;
                *(float2*)(g_Y + (size_t)s0 * DIM + n0 + col) = o;
            }
            if (s1 >= 0) {
                float2 o; o.x = acc[mt][nt][2] + bv.x; o.y = acc[mt][nt][3] + bv.y;
                *(float2*)(g_Y + (size_t)s1 * DIM + n0 + col) = o;
            }
        }
    }
}

// ---------------- kernel 6: combine ------------------------------------------
__global__ void combine_kernel(const float* __restrict__ x, float* __restrict__ out) {
    int idx = blockIdx.x * blockDim.x + threadIdx.x;
    if (idx >= NTOK * DIM / 4) return;
    int n  = idx >> 8;
    int dq = idx & 255;

    float g0 = g_gate[2 * n], g1 = g_gate[2 * n + 1];
    bool  k0 = g_keep[2 * n] != 0, k1 = g_keep[2 * n + 1] != 0;

    float4 xv = ((const float4*)x)[(size_t)n * 256 + dq];
    float4 y0 = k0 ? ((const float4*)g_Y)[(size_t)(2 * n) * 256 + dq]     : xv;
    float4 y1 = k1 ? ((const float4*)g_Y)[(size_t)(2 * n + 1) * 256 + dq] : xv;

    float4 o;
    o.x = g0 * y0.x + g1 * y1.x;
    o.y = g0 * y0.y + g1 * y1.y;
    o.z = g0 * y0.z + g1 * y1.z;
    o.w = g0 * y0.w + g1 * y1.w;
    ((float4*)out)[idx] = o;
}

// ---------------- launch ------------------------------------------------------
extern "C" void kernel_launch(void* const* d_in, const int* in_sizes, int n_in,
                              void* d_out, int out_size) {
    const float* moe_inp  = (const float*)d_in[0];
    const float* gate_w   = (const float*)d_in[1];
    const float* gate_b   = (const float*)d_in[2];
    const float* expert_w = (const float*)d_in[3];
    const float* expert_b = (const float*)d_in[4];
    float* out = (float*)d_out;

    (void)in_sizes; (void)n_in; (void)out_size;

    cudaFuncSetAttribute(moe_gemm_mma, cudaFuncAttributeMaxDynamicSharedMemorySize,
                         GEMM_SMEM);

    init_kernel<<<1, 32>>>();
    gate_kernel<<<NTOK / 8, 256>>>(moe_inp, gate_w, gate_b);
    build_kernel<<<NS / 256, 256>>>();
    rank_kernel<<<dim3(NE, 16), 256>>>();
    convert_w_kernel<<<(NE * DIM * DIM / 4) / 256, 256>>>(expert_w);
    gather_a_kernel<<<dim3(CAPE, NE), 128>>>(moe_inp);
    moe_gemm_mma<<<dim3(DIM / GBN, CAPE / GBM, NE), 256, GEMM_SMEM>>>(expert_b);
    combine_kernel<<<(NTOK * DIM / 4 + 255) / 256, 256>>>(moe_inp, out);
}

// round 8
// speedup vs baseline: 4.6586x; 1.1762x over previous
#include <cuda_runtime.h>
#include <cuda_fp16.h>
#include <math.h>
#include <stdint.h>

// Problem constants
#define NTOK 8192
#define DIM  1024
#define NE   16
#define CAPE 1024
#define NS   (NTOK*2)

// ---------------- scratch (static device globals) ----------------------------
__device__ float              g_gate[NS];
__device__ unsigned long long g_key[NS];
__device__ int                g_eid[NS];
__device__ int                g_cnt[NE];
__device__ int                g_list[NE*NS];
__device__ unsigned long long g_lkey[NE*NS];
__device__ int                g_keptcnt[NE];
__device__ int                g_kept[NE*CAPE];
__device__ unsigned char      g_keep[NS];
__device__ __half             g_Yh[(size_t)NS*DIM];          // 32MB fp16 expert outputs
__device__ __half             g_Ax[(size_t)NTOK*DIM];        // 16MB fp16(x) all tokens
__device__ __half             g_Bw[(size_t)NE*DIM*DIM];      // 32MB flat fp16(w)

// ---------------- helpers (baseline PTX only: sm_80-level features) ----------
__device__ __forceinline__ uint32_t smem_u32(const void* p) {
    uint32_t a;
    asm("{ .reg .u64 t; cvta.to.shared.u64 t, %1; cvt.u32.u64 %0, t; }" : "=r"(a) : "l"(p));
    return a;
}
__device__ __forceinline__ void cp16(uint32_t d, const void* s) {
    asm volatile("cp.async.cg.shared.global [%0], [%1], 16;" :: "r"(d), "l"(s));
}
__device__ __forceinline__ void cp_commit() {
    asm volatile("cp.async.commit_group;" ::: "memory");
}
__device__ __forceinline__ void ldmx4(uint32_t* r, uint32_t addr) {
    asm volatile("ldmatrix.sync.aligned.m8n8.x4.shared.b16 {%0,%1,%2,%3}, [%4];"
                 : "=r"(r[0]), "=r"(r[1]), "=r"(r[2]), "=r"(r[3]) : "r"(addr));
}
__device__ __forceinline__ void mma_f16(float* c, const uint32_t* a, uint32_t b0, uint32_t b1) {
    asm volatile("mma.sync.aligned.m16n8k16.row.col.f32.f16.f16.f32 "
                 "{%0,%1,%2,%3}, {%4,%5,%6,%7}, {%8,%9}, {%0,%1,%2,%3};"
                 : "+f"(c[0]), "+f"(c[1]), "+f"(c[2]), "+f"(c[3])
                 : "r"(a[0]), "r"(a[1]), "r"(a[2]), "r"(a[3]), "r"(b0), "r"(b1));
}

// ---------------- kernel 0: reset counters -----------------------------------
__global__ void init_kernel() {
    int t = threadIdx.x;
    if (t < NE) { g_cnt[t] = 0; g_keptcnt[t] = 0; }
}

// ---------------- kernel 1: gating (one warp per token) ----------------------
__global__ void gate_kernel(const float* __restrict__ x,
                            const float* __restrict__ gw,
                            const float* __restrict__ gb) {
    int warp = (blockIdx.x * blockDim.x + threadIdx.x) >> 5;
    int lane = threadIdx.x & 31;
    if (warp >= NTOK) return;
    const float* xr = x + (size_t)warp * DIM;

    float acc[NE];
#pragma unroll
    for (int e = 0; e < NE; e++) acc[e] = 0.f;

    for (int i = 0; i < DIM / 32; i++) {
        int d = lane + 32 * i;
        float xv = xr[d];
        const float4* g4 = (const float4*)(gw + d * NE);
#pragma unroll
        for (int q = 0; q < 4; q++) {
            float4 w = g4[q];
            acc[4*q+0] += xv * w.x;
            acc[4*q+1] += xv * w.y;
            acc[4*q+2] += xv * w.z;
            acc[4*q+3] += xv * w.w;
        }
    }
#pragma unroll
    for (int e = 0; e < NE; e++) {
        float v = acc[e];
#pragma unroll
        for (int o = 16; o > 0; o >>= 1) v += __shfl_xor_sync(0xffffffffu, v, o);
        acc[e] = v;
    }

    if (lane == 0) {
        float v0 = -1e30f, v1 = -1e30f;
        int   i0 = 0, i1 = 0;
#pragma unroll
        for (int e = 0; e < NE; e++) {
            float v = acc[e] + gb[e];
            if (v > v0)      { v1 = v0; i1 = i0; v0 = v; i0 = e; }
            else if (v > v1) { v1 = v;  i1 = e; }
        }
        float t  = expf(v1 - v0);
        float s  = 1.f / (1.f + t);
        float g0 = s, g1 = t * s;        // g0 >= 0.5 always

        int s0 = 2 * warp, s1 = s0 + 1;
        g_gate[s0] = g0;  g_gate[s1] = g1;
        g_eid[s0]  = i0;  g_eid[s1]  = i1;
        unsigned long long sb = (unsigned long long)__float_as_uint(g0);
        g_key[s0] = (sb << 14) | (unsigned long long)(NS - 1 - s0);
        g_key[s1] = (sb << 14) | (unsigned long long)(NS - 1 - s1);
    }
}

// ---------------- kernel 2: per-expert slot lists -----------------------------
__global__ void build_kernel() {
    int s = blockIdx.x * blockDim.x + threadIdx.x;
    if (s >= NS) return;
    int e = g_eid[s];
    int pos = atomicAdd(&g_cnt[e], 1);
    g_list[e * NS + pos] = s;
    g_lkey[e * NS + pos] = g_key[s];
}

// ---------------- kernel 3: histogram-select capacity ranking ----------------
// One block per expert. Keys' score part (g0) lies in [0.5, 1] -> bits in
// [0x3F000000, 0x3F800000]. bucket = (bits - 0x3F000000) >> 9 is a monotone
// 14-bit map. Suffix-scan histogram -> threshold bucket B. Exact ranking only
// inside bucket B (expected a handful of keys).
#define NBUCK 16384
#define BLCAP 8192
#define RSMEM (NBUCK*4 + BLCAP*8 + BLCAP*4)

__device__ __forceinline__ int key_bucket(unsigned long long k) {
    int diff = (int)(uint32_t)(k >> 14) - 0x3F000000;
    diff >>= 9;
    return diff < 0 ? 0 : (diff > NBUCK - 1 ? NBUCK - 1 : diff);
}

__global__ void rank_kernel() {
    extern __shared__ char rsm[];
    int* hist = (int*)rsm;
    unsigned long long* lkey = (unsigned long long*)(rsm + NBUCK * 4);
    int* lslot = (int*)(rsm + NBUCK * 4 + BLCAP * 8);

    __shared__ int ps[256];
    __shared__ int suf[256];
    __shared__ int sB, sAbove, sNB;

    int e = blockIdx.x;
    int c = g_cnt[e];
    int t = threadIdx.x;

    for (int i = t; i < NBUCK; i += 256) hist[i] = 0;
    if (t == 0) { sB = -1; sAbove = 0; sNB = 0; }
    __syncthreads();

    // pass A: histogram
    for (int i = t; i < c; i += 256)
        atomicAdd(&hist[key_bucket(g_lkey[e * NS + i])], 1);
    __syncthreads();

    // suffix scan over 256 segments of 64 buckets each
    int local = 0;
#pragma unroll 8
    for (int j = 0; j < 64; j++) local += hist[t * 64 + j];
    ps[t] = local;
    __syncthreads();
    if (t == 0) {
        int run = 0;
        for (int j = 255; j >= 0; j--) { suf[j] = run; run += ps[j]; }
    }
    __syncthreads();
    // the unique segment straddling CAPE walks its buckets
    if (suf[t] < CAPE && CAPE <= suf[t] + ps[t]) {
        int running = suf[t];
        for (int j = 63; j >= 0; j--) {
            int b = t * 64 + j;
            int h = hist[b];
            if (running < CAPE && CAPE <= running + h) { sB = b; sAbove = running; }
            running += h;
        }
    }
    __syncthreads();
    int B = sB, above = sAbove;

    // pass B: classify
    for (int i = t; i < c; i += 256) {
        unsigned long long k = g_lkey[e * NS + i];
        int slot = g_list[e * NS + i];
        int b = key_bucket(k);
        if (b > B || B < 0) {
            g_keep[slot] = 1;
            int p = atomicAdd(&g_keptcnt[e], 1);
            g_kept[e * CAPE + p] = slot;
        } else if (b < B) {
            g_keep[slot] = 0;
        } else {
            int p = atomicAdd(&sNB, 1);
            if (p < BLCAP) { lkey[p] = k; lslot[p] = slot; }
            else {
                // overflow fallback: exact rank by global scan
                int cnt = 0;
                for (int j = 0; j < c; j++) cnt += (g_lkey[e * NS + j] > k) ? 1 : 0;
                bool kp = cnt < CAPE;
                g_keep[slot] = kp ? 1 : 0;
                if (kp) { int q = atomicAdd(&g_keptcnt[e], 1); g_kept[e * CAPE + q] = slot; }
            }
        }
    }
    __syncthreads();

    int nb = sNB < BLCAP ? sNB : BLCAP;
    bool overflow = sNB > BLCAP;
    for (int i = t; i < nb; i += 256) {
        unsigned long long k = lkey[i];
        int slot = lslot[i];
        int cnt = above;
        if (!overflow) {
            for (int j = 0; j < nb; j++) cnt += (lkey[j] > k) ? 1 : 0;
        } else {
            cnt = 0;
            for (int j = 0; j < c; j++) cnt += (g_lkey[e * NS + j] > k) ? 1 : 0;
        }
        bool kp = cnt < CAPE;
        g_keep[slot] = kp ? 1 : 0;
        if (kp) { int p = atomicAdd(&g_keptcnt[e], 1); g_kept[e * CAPE + p] = slot; }
    }
}

// ---------------- kernel 4a: convert expert weights to fp16 (flat stream) ----
__global__ void convert_w_kernel(const float* __restrict__ ew) {
    size_t i4 = (size_t)blockIdx.x * blockDim.x + threadIdx.x;
    size_t g  = i4 * 4;
    float4 v  = *(const float4*)(ew + g);
    unsigned short h0 = __half_as_ushort(__float2half_rn(v.x));
    unsigned short h1 = __half_as_ushort(__float2half_rn(v.y));
    unsigned short h2 = __half_as_ushort(__float2half_rn(v.z));
    unsigned short h3 = __half_as_ushort(__float2half_rn(v.w));
    *(uint2*)(g_Bw + g) = make_uint2((uint32_t)h0 | ((uint32_t)h1 << 16),
                                     (uint32_t)h2 | ((uint32_t)h3 << 16));
}

// ---------------- kernel 4b: convert all token rows to fp16 ------------------
__global__ void convert_x_kernel(const float* __restrict__ x) {
    size_t i4 = (size_t)blockIdx.x * blockDim.x + threadIdx.x;
    size_t g  = i4 * 4;
    float4 v  = *(const float4*)(x + g);
    unsigned short h0 = __half_as_ushort(__float2half_rn(v.x));
    unsigned short h1 = __half_as_ushort(__float2half_rn(v.y));
    unsigned short h2 = __half_as_ushort(__float2half_rn(v.z));
    unsigned short h3 = __half_as_ushort(__float2half_rn(v.w));
    *(uint2*)(g_Ax + g) = make_uint2((uint32_t)h0 | ((uint32_t)h1 << 16),
                                     (uint32_t)h2 | ((uint32_t)h3 << 16));
}

// ---------------- kernel 5: warp-MMA (HMMA) expert GEMM, K=1024 --------------
// A rows gathered on the fly from g_Ax via smem token table.
// BM=128, BN=128, BK=32, 3-stage cp.async, 8 warps (4m x 2n), warp tile 32x64.
#define GBM 128
#define GBN 128
#define NKC 32
#define STAGE_BYTES 16384                       // A 8KB + B 8KB
#define GEMM_SMEM (3*STAGE_BYTES + GBM*8)

struct GCtx {
    const __half* Bb;
    const int* stok;       // smem token table
    uint32_t sb;
    int t;
};

__device__ __forceinline__ void g_load(const GCtx& c, int kc) {
    int k0 = kc * 32;
    uint32_t st = c.sb + (kc % 3) * STAGE_BYTES;
#pragma unroll
    for (int j = 0; j < 2; j++) {               // A: 128 rows x 4 chunks(16B)
        int s = c.t + 256 * j;
        int row = s >> 2, ch = s & 3;
        uint32_t dst = st + row * 64 + ((ch ^ ((row >> 1) & 3)) << 4);
        cp16(dst, g_Ax + (size_t)c.stok[row] * DIM + k0 + ch * 8);
    }
#pragma unroll
    for (int j = 0; j < 2; j++) {               // B: 128 rows x 4 chunks(16B)
        int s = c.t + 256 * j;
        int row = s >> 2, ch = s & 3;
        uint32_t dst = st + 8192 + row * 64 + ((ch ^ ((row >> 1) & 3)) << 4);
        cp16(dst, c.Bb + (size_t)row * DIM + k0 + ch * 8);
    }
    cp_commit();
}

__global__ void __launch_bounds__(256, 2)
moe_gemm_mma(const float* __restrict__ eb) {
    extern __shared__ char smem[];
    int e    = blockIdx.z;
    int mcnt = g_keptcnt[e];
    int m0   = blockIdx.y * GBM;
    if (m0 >= mcnt) return;
    int n0   = blockIdx.x * GBN;

    uint32_t sb = smem_u32(smem);
    int t = threadIdx.x;
    int w = t >> 5, l = t & 31;
    int wm = w & 3, wn = w >> 2;

    int* sslot = (int*)(smem + 3 * STAGE_BYTES);
    int* stok  = sslot + GBM;
    if (t < GBM) {
        int mi = m0 + t;
        int slot = (mi < mcnt) ? g_kept[e * CAPE + mi] : -1;
        sslot[t] = slot;
        stok[t]  = (slot >= 0) ? (slot >> 1) : 0;
    }
    __syncthreads();

    GCtx c;
    c.Bb   = g_Bw + (size_t)(e * DIM + n0) * DIM;
    c.stok = stok;
    c.sb   = sb;
    c.t    = t;

    g_load(c, 0);
    g_load(c, 1);

    float acc[2][8][4];
#pragma unroll
    for (int i = 0; i < 2; i++)
#pragma unroll
        for (int j = 0; j < 8; j++)
#pragma unroll
            for (int q = 0; q < 4; q++) acc[i][j][q] = 0.f;

    int sub = l >> 3, lr = l & 7;
    int a_row = wm * 32 + lr + ((sub & 1) << 3);   // + mt*16
    int a_cs  = sub >> 1;
    int b_row = wn * 64 + lr + ((sub >> 1) << 3);  // + j*16
    int b_cs  = sub & 1;

    for (int kc = 0; kc < NKC; kc++) {
        asm volatile("cp.async.wait_group 1;" ::: "memory");
        __syncthreads();
        uint32_t sA = sb + (kc % 3) * STAGE_BYTES;
        uint32_t sB = sA + 8192;
#pragma unroll
        for (int ks = 0; ks < 2; ks++) {
            uint32_t areg[2][4];
#pragma unroll
            for (int mt = 0; mt < 2; mt++) {
                int row = a_row + mt * 16;
                int kch = ks * 2 + a_cs;
                ldmx4(areg[mt], sA + row * 64 + ((kch ^ ((row >> 1) & 3)) << 4));
            }
#pragma unroll
            for (int j = 0; j < 4; j++) {
                int row = b_row + j * 16;
                int kch = ks * 2 + b_cs;
                uint32_t breg[4];
                ldmx4(breg, sB + row * 64 + ((kch ^ ((row >> 1) & 3)) << 4));
#pragma unroll
                for (int mt = 0; mt < 2; mt++) {
                    mma_f16(acc[mt][2*j],   areg[mt], breg[0], breg[1]);
                    mma_f16(acc[mt][2*j+1], areg[mt], breg[2], breg[3]);
                }
            }
        }
        __syncthreads();
        if (kc + 2 < NKC) g_load(c, kc + 2);
        else cp_commit();
    }

    // epilogue: bias + scatter fp16 to per-slot Y
    const float* br = eb + (size_t)e * DIM + n0;
#pragma unroll
    for (int mt = 0; mt < 2; mt++) {
        int r0 = wm * 32 + mt * 16 + (l >> 2);
        int s0 = sslot[r0], s1 = sslot[r0 + 8];
#pragma unroll
        for (int nt = 0; nt < 8; nt++) {
            int col = wn * 64 + nt * 8 + (l & 3) * 2;
            float2 bv = *(const float2*)(br + col);
            if (s0 >= 0) {
                __half2 h = __floats2half2_rn(acc[mt][nt][0] + bv.x, acc[mt][nt][1] + bv.y);
                *(__half2*)(g_Yh + (size_t)s0 * DIM + n0 + col) = h;
            }
            if (s1 >= 0) {
                __half2 h = __floats2half2_rn(acc[mt][nt][2] + bv.x, acc[mt][nt][3] + bv.y);
                *(__half2*)(g_Yh + (size_t)s1 * DIM + n0 + col) = h;
            }
        }
    }
}

// ---------------- kernel 6: combine ------------------------------------------
__global__ void combine_kernel(const float* __restrict__ x, float* __restrict__ out) {
    int idx = blockIdx.x * blockDim.x + threadIdx.x;
    if (idx >= NTOK * DIM / 4) return;
    int n  = idx >> 8;
    int dq = idx & 255;

    float g0 = g_gate[2 * n], g1 = g_gate[2 * n + 1];
    bool  k0 = g_keep[2 * n] != 0, k1 = g_keep[2 * n + 1] != 0;

    float4 xv = ((const float4*)x)[(size_t)n * 256 + dq];

    float y0[4], y1[4];
    if (k0) {
        const __half2* p = (const __half2*)(g_Yh + (size_t)(2 * n) * DIM + dq * 4);
        float2 a = __half22float2(p[0]), b = __half22float2(p[1]);
        y0[0] = a.x; y0[1] = a.y; y0[2] = b.x; y0[3] = b.y;
    } else { y0[0] = xv.x; y0[1] = xv.y; y0[2] = xv.z; y0[3] = xv.w; }
    if (k1) {
        const __half2* p = (const __half2*)(g_Yh + (size_t)(2 * n + 1) * DIM + dq * 4);
        float2 a = __half22float2(p[0]), b = __half22float2(p[1]);
        y1[0] = a.x; y1[1] = a.y; y1[2] = b.x; y1[3] = b.y;
    } else { y1[0] = xv.x; y1[1] = xv.y; y1[2] = xv.z; y1[3] = xv.w; }

    float4 o;
    o.x = g0 * y0[0] + g1 * y1[0];
    o.y = g0 * y0[1] + g1 * y1[1];
    o.z = g0 * y0[2] + g1 * y1[2];
    o.w = g0 * y0[3] + g1 * y1[3];
    ((float4*)out)[idx] = o;
}

// ---------------- launch ------------------------------------------------------
extern "C" void kernel_launch(void* const* d_in, const int* in_sizes, int n_in,
                              void* d_out, int out_size) {
    const float* moe_inp  = (const float*)d_in[0];
    const float* gate_w   = (const float*)d_in[1];
    const float* gate_b   = (const float*)d_in[2];
    const float* expert_w = (const float*)d_in[3];
    const float* expert_b = (const float*)d_in[4];
    float* out = (float*)d_out;

    (void)in_sizes; (void)n_in; (void)out_size;

    cudaFuncSetAttribute(rank_kernel, cudaFuncAttributeMaxDynamicSharedMemorySize, RSMEM);
    cudaFuncSetAttribute(moe_gemm_mma, cudaFuncAttributeMaxDynamicSharedMemorySize,
                         GEMM_SMEM);

    init_kernel<<<1, 32>>>();
    gate_kernel<<<NTOK / 8, 256>>>(moe_inp, gate_w, gate_b);
    convert_x_kernel<<<(NTOK * DIM / 4) / 256, 256>>>(moe_inp);
    convert_w_kernel<<<(NE * DIM * DIM / 4) / 256, 256>>>(expert_w);
    build_kernel<<<NS / 256, 256>>>();
    rank_kernel<<<NE, 256, RSMEM>>>();
    moe_gemm_mma<<<dim3(DIM / GBN, CAPE / GBM, NE), 256, GEMM_SMEM>>>(expert_b);
    combine_kernel<<<(NTOK * DIM / 4 + 255) / 256, 256>>>(moe_inp, out);
}

// round 9
// speedup vs baseline: 4.9612x; 1.0650x over previous
#include <cuda_runtime.h>
#include <cuda_fp16.h>
#include <math.h>
#include <stdint.h>

// Problem constants
#define NTOK 8192
#define DIM  1024
#define NE   16
#define CAPE 1024
#define NS   (NTOK*2)

// ---------------- scratch (static device globals) ----------------------------
__device__ float              g_gate[NS];
__device__ unsigned long long g_key[NS];
__device__ int                g_eid[NS];
__device__ int                g_cnt[NE];
__device__ int                g_list[NE*NS];
__device__ unsigned long long g_lkey[NE*NS];
__device__ int                g_keptcnt[NE];
__device__ int                g_kept[NE*CAPE];
__device__ unsigned char      g_keep[NS];
__device__ __half             g_Yh[(size_t)NS*DIM];          // 32MB fp16 expert outputs
__device__ __half             g_Ax[(size_t)NTOK*DIM];        // 16MB fp16(x) all tokens
__device__ __half             g_Bw[(size_t)NE*DIM*DIM];      // 32MB flat fp16(w)

// ---------------- helpers (baseline PTX only: sm_80-level features) ----------
__device__ __forceinline__ uint32_t smem_u32(const void* p) {
    uint32_t a;
    asm("{ .reg .u64 t; cvta.to.shared.u64 t, %1; cvt.u32.u64 %0, t; }" : "=r"(a) : "l"(p));
    return a;
}
__device__ __forceinline__ void cp16(uint32_t d, const void* s) {
    asm volatile("cp.async.cg.shared.global [%0], [%1], 16;" :: "r"(d), "l"(s));
}
__device__ __forceinline__ void cp_commit() {
    asm volatile("cp.async.commit_group;" ::: "memory");
}
__device__ __forceinline__ void ldmx4(uint32_t* r, uint32_t addr) {
    asm volatile("ldmatrix.sync.aligned.m8n8.x4.shared.b16 {%0,%1,%2,%3}, [%4];"
                 : "=r"(r[0]), "=r"(r[1]), "=r"(r[2]), "=r"(r[3]) : "r"(addr));
}
__device__ __forceinline__ void mma_f16(float* c, const uint32_t* a, uint32_t b0, uint32_t b1) {
    asm volatile("mma.sync.aligned.m16n8k16.row.col.f32.f16.f16.f32 "
                 "{%0,%1,%2,%3}, {%4,%5,%6,%7}, {%8,%9}, {%0,%1,%2,%3};"
                 : "+f"(c[0]), "+f"(c[1]), "+f"(c[2]), "+f"(c[3])
                 : "r"(a[0]), "r"(a[1]), "r"(a[2]), "r"(a[3]), "r"(b0), "r"(b1));
}

// ---------------- kernel 0: reset counters -----------------------------------
__global__ void init_kernel() {
    int t = threadIdx.x;
    if (t < NE) { g_cnt[t] = 0; g_keptcnt[t] = 0; }
}

// ---------------- kernel 1: gating + fp16 convert of x (one warp per token) --
__global__ void gate_kernel(const float* __restrict__ x,
                            const float* __restrict__ gw,
                            const float* __restrict__ gb) {
    int warp = (blockIdx.x * blockDim.x + threadIdx.x) >> 5;
    int lane = threadIdx.x & 31;
    if (warp >= NTOK) return;
    const float* xr = x + (size_t)warp * DIM;

    float acc[NE];
#pragma unroll
    for (int e = 0; e < NE; e++) acc[e] = 0.f;

    for (int i = 0; i < DIM / 32; i++) {
        int d = lane + 32 * i;
        float xv = xr[d];
        const float4* g4 = (const float4*)(gw + d * NE);
#pragma unroll
        for (int q = 0; q < 4; q++) {
            float4 w = g4[q];
            acc[4*q+0] += xv * w.x;
            acc[4*q+1] += xv * w.y;
            acc[4*q+2] += xv * w.z;
            acc[4*q+3] += xv * w.w;
        }
    }

    // fused fp16 convert of this row (re-read from L1, contiguous 16B stores)
    {
        __half* oh = g_Ax + (size_t)warp * DIM;
#pragma unroll
        for (int i = 0; i < 4; i++) {
            int chunk = i * 32 + lane;          // 128 chunks of 8 elems
            float4 v0 = *(const float4*)(xr + chunk * 8);
            float4 v1 = *(const float4*)(xr + chunk * 8 + 4);
            unsigned short h[8] = {
                __half_as_ushort(__float2half_rn(v0.x)), __half_as_ushort(__float2half_rn(v0.y)),
                __half_as_ushort(__float2half_rn(v0.z)), __half_as_ushort(__float2half_rn(v0.w)),
                __half_as_ushort(__float2half_rn(v1.x)), __half_as_ushort(__float2half_rn(v1.y)),
                __half_as_ushort(__float2half_rn(v1.z)), __half_as_ushort(__float2half_rn(v1.w)) };
            *(uint4*)(oh + chunk * 8) =
                make_uint4((uint32_t)h[0] | ((uint32_t)h[1] << 16),
                           (uint32_t)h[2] | ((uint32_t)h[3] << 16),
                           (uint32_t)h[4] | ((uint32_t)h[5] << 16),
                           (uint32_t)h[6] | ((uint32_t)h[7] << 16));
        }
    }

#pragma unroll
    for (int e = 0; e < NE; e++) {
        float v = acc[e];
#pragma unroll
        for (int o = 16; o > 0; o >>= 1) v += __shfl_xor_sync(0xffffffffu, v, o);
        acc[e] = v;
    }

    if (lane == 0) {
        float v0 = -1e30f, v1 = -1e30f;
        int   i0 = 0, i1 = 0;
#pragma unroll
        for (int e = 0; e < NE; e++) {
            float v = acc[e] + gb[e];
            if (v > v0)      { v1 = v0; i1 = i0; v0 = v; i0 = e; }
            else if (v > v1) { v1 = v;  i1 = e; }
        }
        float t  = expf(v1 - v0);
        float s  = 1.f / (1.f + t);
        float g0 = s, g1 = t * s;        // g0 >= 0.5 always

        int s0 = 2 * warp, s1 = s0 + 1;
        g_gate[s0] = g0;  g_gate[s1] = g1;
        g_eid[s0]  = i0;  g_eid[s1]  = i1;
        unsigned long long sb = (unsigned long long)__float_as_uint(g0);
        g_key[s0] = (sb << 14) | (unsigned long long)(NS - 1 - s0);
        g_key[s1] = (sb << 14) | (unsigned long long)(NS - 1 - s1);
    }
}

// ---------------- kernel 2: per-expert slot lists -----------------------------
__global__ void build_kernel() {
    int s = blockIdx.x * blockDim.x + threadIdx.x;
    if (s >= NS) return;
    int e = g_eid[s];
    int pos = atomicAdd(&g_cnt[e], 1);
    g_list[e * NS + pos] = s;
    g_lkey[e * NS + pos] = g_key[s];
}

// ---------------- kernel 3: histogram-select capacity ranking ----------------
#define NBUCK 16384
#define BLCAP 8192
#define RSMEM (NBUCK*4 + BLCAP*8 + BLCAP*4)

__device__ __forceinline__ int key_bucket(unsigned long long k) {
    int diff = (int)(uint32_t)(k >> 14) - 0x3F000000;
    diff >>= 9;
    return diff < 0 ? 0 : (diff > NBUCK - 1 ? NBUCK - 1 : diff);
}

__global__ void rank_kernel() {
    extern __shared__ char rsm[];
    int* hist = (int*)rsm;
    unsigned long long* lkey = (unsigned long long*)(rsm + NBUCK * 4);
    int* lslot = (int*)(rsm + NBUCK * 4 + BLCAP * 8);

    __shared__ int ps[256];
    __shared__ int suf[256];
    __shared__ int sB, sAbove, sNB;

    int e = blockIdx.x;
    int c = g_cnt[e];
    int t = threadIdx.x;

    for (int i = t; i < NBUCK; i += 256) hist[i] = 0;
    if (t == 0) { sB = -1; sAbove = 0; sNB = 0; }
    __syncthreads();

    for (int i = t; i < c; i += 256)
        atomicAdd(&hist[key_bucket(g_lkey[e * NS + i])], 1);
    __syncthreads();

    int local = 0;
#pragma unroll 8
    for (int j = 0; j < 64; j++) local += hist[t * 64 + j];
    ps[t] = local;
    __syncthreads();
    if (t == 0) {
        int run = 0;
        for (int j = 255; j >= 0; j--) { suf[j] = run; run += ps[j]; }
    }
    __syncthreads();
    if (suf[t] < CAPE && CAPE <= suf[t] + ps[t]) {
        int running = suf[t];
        for (int j = 63; j >= 0; j--) {
            int b = t * 64 + j;
            int h = hist[b];
            if (running < CAPE && CAPE <= running + h) { sB = b; sAbove = running; }
            running += h;
        }
    }
    __syncthreads();
    int B = sB, above = sAbove;

    for (int i = t; i < c; i += 256) {
        unsigned long long k = g_lkey[e * NS + i];
        int slot = g_list[e * NS + i];
        int b = key_bucket(k);
        if (b > B || B < 0) {
            g_keep[slot] = 1;
            int p = atomicAdd(&g_keptcnt[e], 1);
            g_kept[e * CAPE + p] = slot;
        } else if (b < B) {
            g_keep[slot] = 0;
        } else {
            int p = atomicAdd(&sNB, 1);
            if (p < BLCAP) { lkey[p] = k; lslot[p] = slot; }
            else {
                int cnt = 0;
                for (int j = 0; j < c; j++) cnt += (g_lkey[e * NS + j] > k) ? 1 : 0;
                bool kp = cnt < CAPE;
                g_keep[slot] = kp ? 1 : 0;
                if (kp) { int q = atomicAdd(&g_keptcnt[e], 1); g_kept[e * CAPE + q] = slot; }
            }
        }
    }
    __syncthreads();

    int nb = sNB < BLCAP ? sNB : BLCAP;
    bool overflow = sNB > BLCAP;
    for (int i = t; i < nb; i += 256) {
        unsigned long long k = lkey[i];
        int slot = lslot[i];
        int cnt = above;
        if (!overflow) {
            for (int j = 0; j < nb; j++) cnt += (lkey[j] > k) ? 1 : 0;
        } else {
            cnt = 0;
            for (int j = 0; j < c; j++) cnt += (g_lkey[e * NS + j] > k) ? 1 : 0;
        }
        bool kp = cnt < CAPE;
        g_keep[slot] = kp ? 1 : 0;
        if (kp) { int p = atomicAdd(&g_keptcnt[e], 1); g_kept[e * CAPE + p] = slot; }
    }
}

// ---------------- kernel 4: convert expert weights to fp16 (8 floats/thread) -
__global__ void convert_w_kernel(const float* __restrict__ ew) {
    size_t i8 = (size_t)blockIdx.x * blockDim.x + threadIdx.x;
    size_t g  = i8 * 8;
    float4 v0 = *(const float4*)(ew + g);
    float4 v1 = *(const float4*)(ew + g + 4);
    unsigned short h[8] = {
        __half_as_ushort(__float2half_rn(v0.x)), __half_as_ushort(__float2half_rn(v0.y)),
        __half_as_ushort(__float2half_rn(v0.z)), __half_as_ushort(__float2half_rn(v0.w)),
        __half_as_ushort(__float2half_rn(v1.x)), __half_as_ushort(__float2half_rn(v1.y)),
        __half_as_ushort(__float2half_rn(v1.z)), __half_as_ushort(__float2half_rn(v1.w)) };
    *(uint4*)(g_Bw + g) =
        make_uint4((uint32_t)h[0] | ((uint32_t)h[1] << 16),
                   (uint32_t)h[2] | ((uint32_t)h[3] << 16),
                   (uint32_t)h[4] | ((uint32_t)h[5] << 16),
                   (uint32_t)h[6] | ((uint32_t)h[7] << 16));
}

// ---------------- kernel 5: warp-MMA (HMMA) expert GEMM, K=1024 --------------
// A rows gathered on the fly from g_Ax via smem token table.
// BM=128, BN=128, BK=32, 4-stage cp.async, single sync per k-chunk.
#define GBM 128
#define GBN 128
#define NKC 32
#define NSTAGE 4
#define STAGE_BYTES 16384                       // A 8KB + B 8KB
#define GEMM_SMEM (NSTAGE*STAGE_BYTES + GBM*8)

struct GCtx {
    const __half* Bb;
    const int* stok;       // smem token table
    uint32_t sb;
    int t;
};

__device__ __forceinline__ void g_load(const GCtx& c, int kc) {
    int k0 = kc * 32;
    uint32_t st = c.sb + (kc % NSTAGE) * STAGE_BYTES;
#pragma unroll
    for (int j = 0; j < 2; j++) {               // A: 128 rows x 4 chunks(16B)
        int s = c.t + 256 * j;
        int row = s >> 2, ch = s & 3;
        uint32_t dst = st + row * 64 + ((ch ^ ((row >> 1) & 3)) << 4);
        cp16(dst, g_Ax + (size_t)c.stok[row] * DIM + k0 + ch * 8);
    }
#pragma unroll
    for (int j = 0; j < 2; j++) {               // B: 128 rows x 4 chunks(16B)
        int s = c.t + 256 * j;
        int row = s >> 2, ch = s & 3;
        uint32_t dst = st + 8192 + row * 64 + ((ch ^ ((row >> 1) & 3)) << 4);
        cp16(dst, c.Bb + (size_t)row * DIM + k0 + ch * 8);
    }
    cp_commit();
}

__global__ void __launch_bounds__(256, 2)
moe_gemm_mma(const float* __restrict__ eb) {
    extern __shared__ char smem[];
    int e    = blockIdx.z;
    int mcnt = g_keptcnt[e];
    int m0   = blockIdx.y * GBM;
    if (m0 >= mcnt) return;
    int n0   = blockIdx.x * GBN;

    uint32_t sb = smem_u32(smem);
    int t = threadIdx.x;
    int w = t >> 5, l = t & 31;
    int wm = w & 3, wn = w >> 2;

    int* sslot = (int*)(smem + NSTAGE * STAGE_BYTES);
    int* stok  = sslot + GBM;
    if (t < GBM) {
        int mi = m0 + t;
        int slot = (mi < mcnt) ? g_kept[e * CAPE + mi] : -1;
        sslot[t] = slot;
        stok[t]  = (slot >= 0) ? (slot >> 1) : 0;
    }
    __syncthreads();

    GCtx c;
    c.Bb   = g_Bw + (size_t)(e * DIM + n0) * DIM;
    c.stok = stok;
    c.sb   = sb;
    c.t    = t;

    g_load(c, 0);
    g_load(c, 1);
    g_load(c, 2);

    float acc[2][8][4];
#pragma unroll
    for (int i = 0; i < 2; i++)
#pragma unroll
        for (int j = 0; j < 8; j++)
#pragma unroll
            for (int q = 0; q < 4; q++) acc[i][j][q] = 0.f;

    int sub = l >> 3, lr = l & 7;
    int a_row = wm * 32 + lr + ((sub & 1) << 3);   // + mt*16
    int a_cs  = sub >> 1;
    int b_row = wn * 64 + lr + ((sub >> 1) << 3);  // + j*16
    int b_cs  = sub & 1;

    for (int kc = 0; kc < NKC; kc++) {
        asm volatile("cp.async.wait_group 2;" ::: "memory");
        __syncthreads();
        // prefetch stage kc+3 (writes stage (kc-1)%4; all warps finished its
        // compute before this iteration's barrier)
        if (kc + 3 < NKC) g_load(c, kc + 3);
        else cp_commit();

        uint32_t sA = sb + (kc % NSTAGE) * STAGE_BYTES;
        uint32_t sB = sA + 8192;
#pragma unroll
        for (int ks = 0; ks < 2; ks++) {
            uint32_t areg[2][4];
#pragma unroll
            for (int mt = 0; mt < 2; mt++) {
                int row = a_row + mt * 16;
                int kch = ks * 2 + a_cs;
                ldmx4(areg[mt], sA + row * 64 + ((kch ^ ((row >> 1) & 3)) << 4));
            }
#pragma unroll
            for (int j = 0; j < 4; j++) {
                int row = b_row + j * 16;
                int kch = ks * 2 + b_cs;
                uint32_t breg[4];
                ldmx4(breg, sB + row * 64 + ((kch ^ ((row >> 1) & 3)) << 4));
#pragma unroll
                for (int mt = 0; mt < 2; mt++) {
                    mma_f16(acc[mt][2*j],   areg[mt], breg[0], breg[1]);
                    mma_f16(acc[mt][2*j+1], areg[mt], breg[2], breg[3]);
                }
            }
        }
    }

    // epilogue: bias + scatter fp16 to per-slot Y
    const float* br = eb + (size_t)e * DIM + n0;
#pragma unroll
    for (int mt = 0; mt < 2; mt++) {
        int r0 = wm * 32 + mt * 16 + (l >> 2);
        int s0 = sslot[r0], s1 = sslot[r0 + 8];
#pragma unroll
        for (int nt = 0; nt < 8; nt++) {
            int col = wn * 64 + nt * 8 + (l & 3) * 2;
            float2 bv = *(const float2*)(br + col);
            if (s0 >= 0) {
                __half2 h = __floats2half2_rn(acc[mt][nt][0] + bv.x, acc[mt][nt][1] + bv.y);
                *(__half2*)(g_Yh + (size_t)s0 * DIM + n0 + col) = h;
            }
            if (s1 >= 0) {
                __half2 h = __floats2half2_rn(acc[mt][nt][2] + bv.x, acc[mt][nt][3] + bv.y);
                *(__half2*)(g_Yh + (size_t)s1 * DIM + n0 + col) = h;
            }
        }
    }
}

// ---------------- kernel 6: combine ------------------------------------------
__global__ void combine_kernel(const float* __restrict__ x, float* __restrict__ out) {
    int idx = blockIdx.x * blockDim.x + threadIdx.x;
    if (idx >= NTOK * DIM / 4) return;
    int n  = idx >> 8;
    int dq = idx & 255;

    float g0 = g_gate[2 * n], g1 = g_gate[2 * n + 1];
    bool  k0 = g_keep[2 * n] != 0, k1 = g_keep[2 * n + 1] != 0;

    float4 xv = ((const float4*)x)[(size_t)n * 256 + dq];

    float y0[4], y1[4];
    if (k0) {
        const __half2* p = (const __half2*)(g_Yh + (size_t)(2 * n) * DIM + dq * 4);
        float2 a = __half22float2(p[0]), b = __half22float2(p[1]);
        y0[0] = a.x; y0[1] = a.y; y0[2] = b.x; y0[3] = b.y;
    } else { y0[0] = xv.x; y0[1] = xv.y; y0[2] = xv.z; y0[3] = xv.w; }
    if (k1) {
        const __half2* p = (const __half2*)(g_Yh + (size_t)(2 * n + 1) * DIM + dq * 4);
        float2 a = __half22float2(p[0]), b = __half22float2(p[1]);
        y1[0] = a.x; y1[1] = a.y; y1[2] = b.x; y1[3] = b.y;
    } else { y1[0] = xv.x; y1[1] = xv.y; y1[2] = xv.z; y1[3] = xv.w; }

    float4 o;
    o.x = g0 * y0[0] + g1 * y1[0];
    o.y = g0 * y0[1] + g1 * y1[1];
    o.z = g0 * y0[2] + g1 * y1[2];
    o.w = g0 * y0[3] + g1 * y1[3];
    ((float4*)out)[idx] = o;
}

// ---------------- launch ------------------------------------------------------
extern "C" void kernel_launch(void* const* d_in, const int* in_sizes, int n_in,
                              void* d_out, int out_size) {
    const float* moe_inp  = (const float*)d_in[0];
    const float* gate_w   = (const float*)d_in[1];
    const float* gate_b   = (const float*)d_in[2];
    const float* expert_w = (const float*)d_in[3];
    const float* expert_b = (const float*)d_in[4];
    float* out = (float*)d_out;

    (void)in_sizes; (void)n_in; (void)out_size;

    cudaFuncSetAttribute(rank_kernel, cudaFuncAttributeMaxDynamicSharedMemorySize, RSMEM);
    cudaFuncSetAttribute(moe_gemm_mma, cudaFuncAttributeMaxDynamicSharedMemorySize,
                         GEMM_SMEM);

    init_kernel<<<1, 32>>>();
    gate_kernel<<<NTOK / 8, 256>>>(moe_inp, gate_w, gate_b);
    convert_w_kernel<<<(NE * DIM * DIM / 8) / 256, 256>>>(expert_w);
    build_kernel<<<NS / 256, 256>>>();
    rank_kernel<<<NE, 256, RSMEM>>>();
    moe_gemm_mma<<<dim3(DIM / GBN, CAPE / GBM, NE), 256, GEMM_SMEM>>>(expert_b);
    combine_kernel<<<(NTOK * DIM / 4 + 255) / 256, 256>>>(moe_inp, out);
}